// round 13
// baseline (speedup 1.0000x reference)
#include <cuda_runtime.h>
#include <cuda_bf16.h>
#include <math.h>
#include <stdint.h>

// Problem constants
#define BB   2
#define SS   2048
#define EE   1024
#define HH   16
#define HD   64
#define DFF  4096
#define MM   (BB*SS)   // 4096 tokens

// ---------------- scratch (device globals; no allocations allowed) ----------
__device__ __align__(128) float g_x1[(size_t)MM*EE];     // residual after attn

__device__ __align__(128) __nv_bfloat16 g_qh [(size_t)MM*EE],  g_ql [(size_t)MM*EE];  // [B,H,S,HD]
__device__ __align__(128) __nv_bfloat16 g_kh [(size_t)MM*EE],  g_kl [(size_t)MM*EE];  // [B,H,S,HD]
__device__ __align__(128) __nv_bfloat16 g_vh [(size_t)MM*EE],  g_vl [(size_t)MM*EE];  // [B,H,S,HD]

__device__ __align__(128) __nv_bfloat16 g_ln_hi [(size_t)MM*EE],  g_ln_lo [(size_t)MM*EE];
__device__ __align__(128) __nv_bfloat16 g_at_hi [(size_t)MM*EE],  g_at_lo [(size_t)MM*EE];
__device__ __align__(128) __nv_bfloat16 g_act_hi[(size_t)MM*DFF], g_act_lo[(size_t)MM*DFF];

__device__ __align__(128) __nv_bfloat16 g_wqkv_hi[(size_t)3*EE*EE], g_wqkv_lo[(size_t)3*EE*EE];
__device__ __align__(128) __nv_bfloat16 g_wao_hi [(size_t)EE*EE],   g_wao_lo [(size_t)EE*EE];
__device__ __align__(128) __nv_bfloat16 g_wfc_hi [(size_t)DFF*EE],  g_wfc_lo [(size_t)DFF*EE];
__device__ __align__(128) __nv_bfloat16 g_wpo_hi [(size_t)EE*DFF],  g_wpo_lo [(size_t)EE*DFF];

// ---------------- helpers ----------------------------------------------------
__device__ __forceinline__ uint32_t smem_u32(const void* p) {
    uint32_t a;
    asm("{ .reg .u64 t; cvta.to.shared.u64 t, %1; cvt.u32.u64 %0, t; }"
        : "=r"(a) : "l"(p));
    return a;
}
__device__ __forceinline__ void cp16(uint32_t saddr, const void* gptr) {
    asm volatile("cp.async.cg.shared.global [%0], [%1], 16;"
                 :: "r"(saddr), "l"(gptr));
}
__device__ __forceinline__ void cp_commit() {
    asm volatile("cp.async.commit_group;" ::: "memory");
}
__device__ __forceinline__ void cp_wait0() {
    asm volatile("cp.async.wait_group 0;" ::: "memory");
}
__device__ __forceinline__ void ldsm4(uint32_t& r0, uint32_t& r1, uint32_t& r2,
                                      uint32_t& r3, uint32_t addr) {
    asm volatile("ldmatrix.sync.aligned.m8n8.x4.shared.b16 {%0,%1,%2,%3}, [%4];"
                 : "=r"(r0), "=r"(r1), "=r"(r2), "=r"(r3) : "r"(addr));
}
__device__ __forceinline__ void ldsm4t(uint32_t& r0, uint32_t& r1, uint32_t& r2,
                                       uint32_t& r3, uint32_t addr) {
    asm volatile("ldmatrix.sync.aligned.m8n8.x4.trans.shared.b16 {%0,%1,%2,%3}, [%4];"
                 : "=r"(r0), "=r"(r1), "=r"(r2), "=r"(r3) : "r"(addr));
}
__device__ __forceinline__ void mma16816(float* c, const uint32_t* a,
                                         uint32_t b0, uint32_t b1) {
    asm volatile(
        "mma.sync.aligned.m16n8k16.row.col.f32.bf16.bf16.f32 "
        "{%0,%1,%2,%3}, {%4,%5,%6,%7}, {%8,%9}, {%0,%1,%2,%3};"
        : "+f"(c[0]), "+f"(c[1]), "+f"(c[2]), "+f"(c[3])
        : "r"(a[0]), "r"(a[1]), "r"(a[2]), "r"(a[3]), "r"(b0), "r"(b1));
}

__device__ __forceinline__ float gelu_tanh(float x) {
    const float c = 0.7978845608028654f;
    return 0.5f * x * (1.0f + tanhf(c * (x + 0.044715f * x * x * x)));
}
__device__ __forceinline__ void split_bf16(float v, __nv_bfloat16& h, __nv_bfloat16& l) {
    h = __float2bfloat16(v);
    l = __float2bfloat16(v - __bfloat162float(h));
}
__device__ __forceinline__ uint32_t pack_bf16(__nv_bfloat16 a, __nv_bfloat16 b) {
    uint16_t ua = *reinterpret_cast<uint16_t*>(&a);
    uint16_t ub = *reinterpret_cast<uint16_t*>(&b);
    return (uint32_t)ua | ((uint32_t)ub << 16);
}

// ---------------- LayerNorm: row -> hi/lo bf16 -------------------------------
__global__ __launch_bounds__(256) void ln_kernel(
    const float* __restrict__ x, const float* __restrict__ g,
    const float* __restrict__ b, __nv_bfloat16* __restrict__ oh,
    __nv_bfloat16* __restrict__ ol)
{
    const int row = blockIdx.x;
    const int t   = threadIdx.x;
    const float4 v = ((const float4*)(x + (size_t)row * EE))[t];

    float s  = v.x + v.y + v.z + v.w;
    float ss = v.x*v.x + v.y*v.y + v.z*v.z + v.w*v.w;

    __shared__ float ws[8], wss[8];
    __shared__ float s_mu, s_rstd;
    const unsigned lane = t & 31u, w = t >> 5;
    #pragma unroll
    for (int off = 16; off; off >>= 1) {
        s  += __shfl_down_sync(0xffffffffu, s,  off);
        ss += __shfl_down_sync(0xffffffffu, ss, off);
    }
    if (lane == 0) { ws[w] = s; wss[w] = ss; }
    __syncthreads();
    if (t == 0) {
        float ts = 0.f, tss = 0.f;
        #pragma unroll
        for (int i = 0; i < 8; i++) { ts += ws[i]; tss += wss[i]; }
        const float mu  = ts * (1.0f / EE);
        const float var = tss * (1.0f / EE) - mu * mu;
        s_mu = mu; s_rstd = rsqrtf(var + 1e-5f);
    }
    __syncthreads();
    const float mu = s_mu, rstd = s_rstd;
    const float4 gg = ((const float4*)g)[t];
    const float4 bb = ((const float4*)b)[t];
    float o0 = (v.x - mu)*rstd*gg.x + bb.x;
    float o1 = (v.y - mu)*rstd*gg.y + bb.y;
    float o2 = (v.z - mu)*rstd*gg.z + bb.z;
    float o3 = (v.w - mu)*rstd*gg.w + bb.w;
    const size_t base = (size_t)row * EE + t * 4;
    __nv_bfloat16 h, l;
    split_bf16(o0, h, l); oh[base+0] = h; ol[base+0] = l;
    split_bf16(o1, h, l); oh[base+1] = h; ol[base+1] = l;
    split_bf16(o2, h, l); oh[base+2] = h; ol[base+2] = l;
    split_bf16(o3, h, l); oh[base+3] = h; ol[base+3] = l;
}

// ---------------- fused weight fp32 -> hi/lo bf16 (all 4 weights) ------------
#define N4_QKV  (3*EE*EE/4)
#define N4_AO   (EE*EE/4)
#define N4_FC   (DFF*EE/4)
#define N4_PO   (EE*DFF/4)
#define N4_ALL  (N4_QKV + N4_AO + N4_FC + N4_PO)

__global__ __launch_bounds__(256) void cvt_all_kernel(
    const float* __restrict__ s_qkv, const float* __restrict__ s_ao,
    const float* __restrict__ s_fc,  const float* __restrict__ s_po)
{
    int i = blockIdx.x * 256 + threadIdx.x;
    if (i >= N4_ALL) return;
    const float* src;
    __nv_bfloat16 *hi, *lo;
    if (i < N4_QKV)                      { src = s_qkv; hi = g_wqkv_hi; lo = g_wqkv_lo; }
    else if (i < N4_QKV + N4_AO)         { i -= N4_QKV; src = s_ao; hi = g_wao_hi; lo = g_wao_lo; }
    else if (i < N4_QKV + N4_AO + N4_FC) { i -= N4_QKV + N4_AO; src = s_fc; hi = g_wfc_hi; lo = g_wfc_lo; }
    else                                 { i -= N4_QKV + N4_AO + N4_FC; src = s_po; hi = g_wpo_hi; lo = g_wpo_lo; }
    const float4 v = ((const float4*)src)[i];
    __nv_bfloat16 h, l;
    const size_t base = (size_t)i * 4;
    split_bf16(v.x, h, l); hi[base+0] = h; lo[base+0] = l;
    split_bf16(v.y, h, l); hi[base+1] = h; lo[base+1] = l;
    split_bf16(v.z, h, l); hi[base+2] = h; lo[base+2] = l;
    split_bf16(v.w, h, l); hi[base+3] = h; lo[base+3] = l;
}

// ---------------- HMMA bf16x3 GEMM -------------------------------------------
// C[M,N] = A[M,K] @ W[N,K]^T via AhBh + AhBl + AlBh.
// 128x256 block tile, BK=64, 256 threads = 8 warps (2m x 4n of 64x64),
// 2-stage cp.async, single sync per chunk (attention-shaped config:
// 8 warps, ~200 regs, MMA:LDSM = 6:1).
#define BM 128
#define BN 256
#define BK 64
#define GT 256
#define STAGE_BYTES 98304
#define GEMM_SMEM   (2*STAGE_BYTES) // 196608

template<int MODE>
__global__ __launch_bounds__(GT, 1)
void hmma_gemm(const __nv_bfloat16* __restrict__ Ah, const __nv_bfloat16* __restrict__ Al,
               const __nv_bfloat16* __restrict__ Wh, const __nv_bfloat16* __restrict__ Wl,
               const float* __restrict__ bias, const float* __restrict__ res,
               float* __restrict__ out, int N, int K)
{
    extern __shared__ char smem[];
    const uint32_t sb = smem_u32(smem);
    const int tid  = threadIdx.x;
    const int wid  = tid >> 5;
    const int lane = tid & 31;
    const int m0 = blockIdx.y * BM, n0 = blockIdx.x * BN;
    const int warp_m0 = (wid & 1) * 64;   // 2 warps along m (64 rows)
    const int warp_n0 = (wid >> 1) * 64;  // 4 warps along n (64 cols)

    const int nch = K / BK;

    // per stage: 6144 x 16B units: A hi/lo (1024 each), B hi/lo (2048 each)
    auto load_chunk = [&](int stage, int k0) {
        #pragma unroll
        for (int qq = 0; qq < 24; qq++) {
            const int it = tid + qq * GT;       // 0..6143
            uint32_t soff;
            const __nv_bfloat16* gp;
            if (it < 2048) {                    // A
                const int hl  = it >> 10;
                const int idx = it & 1023;
                const int r   = idx >> 3;
                const int u   = idx & 7;
                gp = (hl ? Al : Ah) + (size_t)(m0 + r) * K + k0 + u * 8;
                soff = stage * STAGE_BYTES + hl * 16384 + r * 128 +
                       ((u ^ (r & 7)) * 16);
            } else {                            // B
                const int it2 = it - 2048;
                const int hl  = it2 >> 11;
                const int idx = it2 & 2047;
                const int r   = idx >> 3;
                const int u   = idx & 7;
                gp = (hl ? Wl : Wh) + (size_t)(n0 + r) * K + k0 + u * 8;
                soff = stage * STAGE_BYTES + 32768 + hl * 32768 + r * 128 +
                       ((u ^ (r & 7)) * 16);
            }
            cp16(sb + soff, gp);
        }
    };

    float acc[4][8][4];
    #pragma unroll
    for (int i = 0; i < 4; i++)
        #pragma unroll
        for (int j = 0; j < 8; j++)
            #pragma unroll
            for (int e = 0; e < 4; e++) acc[i][j][e] = 0.f;

    load_chunk(0, 0);   cp_commit();

    const int g  = lane >> 3;
    const int tg = lane & 7;
    const int rowA_off = (g & 1) * 8 + tg;
    const int rowB_off = (g >> 1) * 8 + tg;

    for (int c = 0; c < nch; c++) {
        cp_wait0();          // chunk c resident (only group in flight)
        __syncthreads();     // all warps done with buf (c+1)&1 (chunk c-1)
        if (c + 1 < nch) load_chunk((c + 1) & 1, (c + 1) * BK);
        cp_commit();         // loads for c+1 overlap compute of c

        const uint32_t stA = sb + (c & 1) * STAGE_BYTES;
        const uint32_t stB = stA + 32768;

        #pragma unroll
        for (int kk = 0; kk < 4; kk++) {
            uint32_t ah[4][4], al[4][4];
            const int unitA = kk * 2 + (g >> 1);
            #pragma unroll
            for (int tm = 0; tm < 4; tm++) {
                const int r = warp_m0 + tm * 16 + rowA_off;
                const uint32_t a = stA + r * 128 + ((unitA ^ (r & 7)) * 16);
                ldsm4(ah[tm][0], ah[tm][1], ah[tm][2], ah[tm][3], a);
                ldsm4(al[tm][0], al[tm][1], al[tm][2], al[tm][3], a + 16384);
            }
            const int unitB = kk * 2 + (g & 1);
            #pragma unroll
            for (int bn = 0; bn < 4; bn++) {
                const int r = warp_n0 + bn * 16 + rowB_off;
                const uint32_t a = stB + r * 128 + ((unitB ^ (r & 7)) * 16);
                uint32_t bh[4], bl[4];
                ldsm4(bh[0], bh[1], bh[2], bh[3], a);
                ldsm4(bl[0], bl[1], bl[2], bl[3], a + 32768);
                #pragma unroll
                for (int tm = 0; tm < 4; tm++) {
                    mma16816(acc[tm][2*bn],   ah[tm], bh[0], bh[1]);
                    mma16816(acc[tm][2*bn],   ah[tm], bl[0], bl[1]);
                    mma16816(acc[tm][2*bn],   al[tm], bh[0], bh[1]);
                    mma16816(acc[tm][2*bn+1], ah[tm], bh[2], bh[3]);
                    mma16816(acc[tm][2*bn+1], ah[tm], bl[2], bl[3]);
                    mma16816(acc[tm][2*bn+1], al[tm], bh[2], bh[3]);
                }
            }
        }
    }

    // ---- epilogue ----
    const int r_lo = lane >> 2;
    const int c_lo = (lane & 3) * 2;
    #pragma unroll
    for (int tm = 0; tm < 4; tm++) {
        #pragma unroll
        for (int tn = 0; tn < 8; tn++) {
            const int n = n0 + warp_n0 + tn * 8 + c_lo;
            #pragma unroll
            for (int h = 0; h < 2; h++) {
                const int m = m0 + warp_m0 + tm * 16 + r_lo + h * 8;
                float v0 = acc[tm][tn][h * 2 + 0] + bias[n];
                float v1 = acc[tm][tn][h * 2 + 1] + bias[n + 1];
                if (MODE == 0) {
                    // all of Q/K/V stored hi-lo [B,H,S,HD] (packed stores)
                    const int head  = n / (3 * HD);
                    const int rem   = n % (3 * HD);
                    const int which = rem / HD;
                    const int d     = rem % HD;      // even
                    const int bI    = m / SS;
                    const int sI    = m % SS;
                    __nv_bfloat16 h0, l0, h1, l1;
                    split_bf16(v0, h0, l0);
                    split_bf16(v1, h1, l1);
                    const size_t dst = (((size_t)bI * HH + head) * SS + sI) * HD + d;
                    __nv_bfloat16* ph = (which == 0) ? g_qh : (which == 1) ? g_kh : g_vh;
                    __nv_bfloat16* pl = (which == 0) ? g_ql : (which == 1) ? g_kl : g_vl;
                    *(uint32_t*)(ph + dst) = pack_bf16(h0, h1);
                    *(uint32_t*)(pl + dst) = pack_bf16(l0, l1);
                } else if (MODE == 1 || MODE == 3) {
                    const size_t o = (size_t)m * N + n;
                    const float2 rr = *(const float2*)(res + o);
                    float2 ov; ov.x = v0 + rr.x; ov.y = v1 + rr.y;
                    *(float2*)(out + o) = ov;
                } else { // MODE 2: gelu -> hi/lo bf16
                    const size_t o = (size_t)m * N + n;
                    __nv_bfloat16 hh, ll;
                    float gv0 = gelu_tanh(v0), gv1 = gelu_tanh(v1);
                    split_bf16(gv0, hh, ll); g_act_hi[o]   = hh; g_act_lo[o]   = ll;
                    split_bf16(gv1, hh, ll); g_act_hi[o+1] = hh; g_act_lo[o+1] = ll;
                }
            }
        }
    }
}

// ---------------- HMMA flash attention (causal) ------------------------------
// Block: 128 queries, 8 warps (16 rows each), kv tiles of 64, double-buffered,
// single sync per tile. Q/K/V all hi-lo [B,H,S,HD]. V frags via ldmatrix.trans.
#define AQ  128
#define AKV 64
#define SQ_H 0
#define SQ_L 16384
#define SST(s) (32768 + (s)*32768)
#define SV_OFF 16384   // K at 0/8192 hi/lo, V at 16384/24576
#define ATTN_SMEM 98304

__global__ __launch_bounds__(256, 1) void attn_mma(
    const __nv_bfloat16* __restrict__ Qh, const __nv_bfloat16* __restrict__ Ql,
    const __nv_bfloat16* __restrict__ Kh, const __nv_bfloat16* __restrict__ Kl,
    const __nv_bfloat16* __restrict__ Vh, const __nv_bfloat16* __restrict__ Vl,
    __nv_bfloat16* __restrict__ Oh, __nv_bfloat16* __restrict__ Ol)
{
    extern __shared__ char smem[];
    const uint32_t sb = smem_u32(smem);
    const int tid  = threadIdx.x;
    const int wid  = tid >> 5;
    const int lane = tid & 31;
    const int bh   = blockIdx.y;
    const int q0   = blockIdx.x * AQ;
    const int g  = lane >> 3;
    const int tg = lane & 7;

    const __nv_bfloat16* Qhb = Qh + (size_t)bh * SS * HD;
    const __nv_bfloat16* Qlb = Ql + (size_t)bh * SS * HD;
    const __nv_bfloat16* Khb = Kh + (size_t)bh * SS * HD;
    const __nv_bfloat16* Klb = Kl + (size_t)bh * SS * HD;
    const __nv_bfloat16* Vhb = Vh + (size_t)bh * SS * HD;
    const __nv_bfloat16* Vlb = Vl + (size_t)bh * SS * HD;

    // ---- Q tile load (hi/lo, 128x64, swizzled) ----
    #pragma unroll
    for (int qq = 0; qq < 8; qq++) {
        const int it = tid + qq * 256;     // 0..2047
        const int hl = it >> 10;
        const int r  = (it >> 3) & 127;
        const int u  = it & 7;
        const __nv_bfloat16* src = (hl ? Qlb : Qhb) + (size_t)(q0 + r) * HD + u * 8;
        cp16(sb + (hl ? SQ_L : SQ_H) + r * 128 + ((u ^ (r & 7)) * 16), src);
    }

    const int nkv = 2 * blockIdx.x + 2;

    auto load_kv = [&](int stage, int kv0) {
        #pragma unroll
        for (int qq = 0; qq < 8; qq++) {
            const int it  = tid + qq * 256;
            const int mat = it >> 9;          // 0 Kh, 1 Kl, 2 Vh, 3 Vl
            const int r   = (it >> 3) & 63;
            const int u   = it & 7;
            const __nv_bfloat16* src;
            if (mat == 0)      src = Khb + (size_t)(kv0 + r) * HD + u * 8;
            else if (mat == 1) src = Klb + (size_t)(kv0 + r) * HD + u * 8;
            else if (mat == 2) src = Vhb + (size_t)(kv0 + r) * HD + u * 8;
            else               src = Vlb + (size_t)(kv0 + r) * HD + u * 8;
            cp16(sb + SST(stage) + mat * 8192 + r * 128 + ((u ^ (r & 7)) * 16), src);
        }
    };

    load_kv(0, 0);
    cp_commit();        // single group: Q + kv0
    cp_wait0();
    __syncthreads();

    // ---- Q fragments to registers (Q region never overwritten) ----
    uint32_t qfh[4][4], qfl[4][4];
    const int rowA_off = (g & 1) * 8 + tg;
    {
        #pragma unroll
        for (int t = 0; t < 4; t++) {
            const int r  = wid * 16 + rowA_off;
            const int uA = t * 2 + (g >> 1);
            const uint32_t a = sb + SQ_H + r * 128 + ((uA ^ (r & 7)) * 16);
            ldsm4(qfh[t][0], qfh[t][1], qfh[t][2], qfh[t][3], a);
            ldsm4(qfl[t][0], qfl[t][1], qfl[t][2], qfl[t][3], a + 16384);
        }
    }

    float m_i[2] = {-1e30f, -1e30f};
    float l_i[2] = {0.f, 0.f};
    float acc_o[8][4];
    #pragma unroll
    for (int nt = 0; nt < 8; nt++)
        #pragma unroll
        for (int e = 0; e < 4; e++) acc_o[nt][e] = 0.f;

    const int rowB_off = (g >> 1) * 8 + tg;

    for (int j = 0; j < nkv; j++) {
        const int kv0 = j * AKV;
        if (j > 0) { cp_wait0(); __syncthreads(); }
        if (j + 1 < nkv) { load_kv((j + 1) & 1, (j + 1) * AKV); cp_commit(); }

        const uint32_t st = sb + SST(j & 1);

        // ---- S = Q K^T (3-pass hi/lo) ----
        float accs[8][4];
        #pragma unroll
        for (int nt = 0; nt < 8; nt++)
            #pragma unroll
            for (int e = 0; e < 4; e++) accs[nt][e] = 0.f;

        #pragma unroll
        for (int t = 0; t < 4; t++) {
            const int uB = t * 2 + (g & 1);
            #pragma unroll
            for (int bn = 0; bn < 4; bn++) {
                const int r = bn * 16 + rowB_off;
                const uint32_t a = st + r * 128 + ((uB ^ (r & 7)) * 16);
                uint32_t kbh[4], kbl[4];
                ldsm4(kbh[0], kbh[1], kbh[2], kbh[3], a);
                ldsm4(kbl[0], kbl[1], kbl[2], kbl[3], a + 8192);
                mma16816(accs[2*bn],   qfh[t], kbh[0], kbh[1]);
                mma16816(accs[2*bn],   qfh[t], kbl[0], kbl[1]);
                mma16816(accs[2*bn],   qfl[t], kbh[0], kbh[1]);
                mma16816(accs[2*bn+1], qfh[t], kbh[2], kbh[3]);
                mma16816(accs[2*bn+1], qfh[t], kbl[2], kbl[3]);
                mma16816(accs[2*bn+1], qfl[t], kbh[2], kbh[3]);
            }
        }
        #pragma unroll
        for (int nt = 0; nt < 8; nt++)
            #pragma unroll
            for (int e = 0; e < 4; e++) accs[nt][e] *= 0.125f;

        // ---- causal mask (only on near-diagonal tiles for this warp) ----
        if (kv0 + AKV - 1 > q0 + wid * 16) {
            #pragma unroll
            for (int nt = 0; nt < 8; nt++)
                #pragma unroll
                for (int e = 0; e < 4; e++) {
                    const int row = q0 + wid * 16 + (lane >> 2) + ((e >> 1) ? 8 : 0);
                    const int col = kv0 + nt * 8 + 2 * (lane & 3) + (e & 1);
                    if (col > row) accs[nt][e] = -1e30f;
                }
        }

        // ---- online softmax (rows r and r+8 per thread) ----
        #pragma unroll
        for (int h = 0; h < 2; h++) {
            float rm = -1e30f;
            #pragma unroll
            for (int nt = 0; nt < 8; nt++)
                rm = fmaxf(rm, fmaxf(accs[nt][2*h], accs[nt][2*h+1]));
            rm = fmaxf(rm, __shfl_xor_sync(0xffffffffu, rm, 1));
            rm = fmaxf(rm, __shfl_xor_sync(0xffffffffu, rm, 2));
            const float mnew = fmaxf(m_i[h], rm);
            const float corr = __expf(m_i[h] - mnew);
            m_i[h] = mnew;
            float rs = 0.f;
            #pragma unroll
            for (int nt = 0; nt < 8; nt++) {
                accs[nt][2*h]   = __expf(accs[nt][2*h]   - mnew);
                accs[nt][2*h+1] = __expf(accs[nt][2*h+1] - mnew);
                rs += accs[nt][2*h] + accs[nt][2*h+1];
            }
            rs += __shfl_xor_sync(0xffffffffu, rs, 1);
            rs += __shfl_xor_sync(0xffffffffu, rs, 2);
            l_i[h] = l_i[h] * corr + rs;
            #pragma unroll
            for (int nt = 0; nt < 8; nt++) {
                acc_o[nt][2*h]   *= corr;
                acc_o[nt][2*h+1] *= corr;
            }
        }

        // ---- pack P to hi/lo A-fragments ----
        uint32_t pfh[4][4], pfl[4][4];
        #pragma unroll
        for (int t = 0; t < 4; t++) {
            #pragma unroll
            for (int half = 0; half < 2; half++) {
                const int nt = 2 * t + half;
                __nv_bfloat16 h0, l0, h1, l1, h2, l2, h3, l3;
                split_bf16(accs[nt][0], h0, l0);
                split_bf16(accs[nt][1], h1, l1);
                split_bf16(accs[nt][2], h2, l2);
                split_bf16(accs[nt][3], h3, l3);
                pfh[t][half*2+0] = pack_bf16(h0, h1);
                pfh[t][half*2+1] = pack_bf16(h2, h3);
                pfl[t][half*2+0] = pack_bf16(l0, l1);
                pfl[t][half*2+1] = pack_bf16(l2, l3);
            }
        }

        // ---- O += P V (3-pass hi/lo). V tile [kv][d]; B-frags via ldsm.trans ----
        #pragma unroll
        for (int t = 0; t < 4; t++) {
            #pragma unroll
            for (int bn = 0; bn < 4; bn++) {
                const int r = t * 16 + rowA_off;             // kv row
                const int u = bn * 2 + (g >> 1);             // d unit
                const uint32_t a = st + SV_OFF + r * 128 + ((u ^ (r & 7)) * 16);
                uint32_t vbh[4], vbl[4];
                ldsm4t(vbh[0], vbh[1], vbh[2], vbh[3], a);
                ldsm4t(vbl[0], vbl[1], vbl[2], vbl[3], a + 8192);
                mma16816(acc_o[2*bn],   pfh[t], vbh[0], vbh[1]);
                mma16816(acc_o[2*bn],   pfh[t], vbl[0], vbl[1]);
                mma16816(acc_o[2*bn],   pfl[t], vbh[0], vbh[1]);
                mma16816(acc_o[2*bn+1], pfh[t], vbh[2], vbh[3]);
                mma16816(acc_o[2*bn+1], pfh[t], vbl[2], vbl[3]);
                mma16816(acc_o[2*bn+1], pfl[t], vbh[2], vbh[3]);
            }
        }
    }

    // ---- epilogue: O / l_i -> at hi/lo [B,S,E] ----
    const int bI = bh / HH;
    const int hI = bh % HH;
    #pragma unroll
    for (int h = 0; h < 2; h++) {
        const float inv = 1.0f / l_i[h];
        const int sI = q0 + wid * 16 + (lane >> 2) + h * 8;
        const size_t base = ((size_t)bI * SS + sI) * EE + hI * HD;
        #pragma unroll
        for (int nt = 0; nt < 8; nt++) {
            const int d = nt * 8 + 2 * (lane & 3);
            __nv_bfloat16 h0, l0, h1, l1;
            split_bf16(acc_o[nt][2*h]   * inv, h0, l0);
            split_bf16(acc_o[nt][2*h+1] * inv, h1, l1);
            *(uint32_t*)(Oh + base + d) = pack_bf16(h0, h1);
            *(uint32_t*)(Ol + base + d) = pack_bf16(l0, l1);
        }
    }
}

// ---------------- launch ----------------------------------------------------
extern "C" void kernel_launch(void* const* d_in, const int* in_sizes, int n_in,
                              void* d_out, int out_size)
{
    const float* x     = (const float*)d_in[0];
    const float* ln1_g = (const float*)d_in[1];
    const float* ln1_b = (const float*)d_in[2];
    const float* ln2_g = (const float*)d_in[3];
    const float* ln2_b = (const float*)d_in[4];
    const float* w_qkv = (const float*)d_in[5];
    const float* b_qkv = (const float*)d_in[6];
    const float* w_ao  = (const float*)d_in[7];
    const float* b_ao  = (const float*)d_in[8];
    const float* w_fc  = (const float*)d_in[9];
    const float* b_fc  = (const float*)d_in[10];
    const float* w_po  = (const float*)d_in[11];
    const float* b_po  = (const float*)d_in[12];
    float* out = (float*)d_out;

    float *x1;
    __nv_bfloat16 *qh, *ql, *kh, *kl, *vh, *vl;
    __nv_bfloat16 *lnh, *lnl, *ath, *atl, *acth, *actl;
    __nv_bfloat16 *wqh, *wql, *waoh, *waol, *wfh, *wfl, *wph, *wpl;
    cudaGetSymbolAddress((void**)&x1,  g_x1);
    cudaGetSymbolAddress((void**)&qh,  g_qh);
    cudaGetSymbolAddress((void**)&ql,  g_ql);
    cudaGetSymbolAddress((void**)&kh,  g_kh);
    cudaGetSymbolAddress((void**)&kl,  g_kl);
    cudaGetSymbolAddress((void**)&vh,  g_vh);
    cudaGetSymbolAddress((void**)&vl,  g_vl);
    cudaGetSymbolAddress((void**)&lnh, g_ln_hi);
    cudaGetSymbolAddress((void**)&lnl, g_ln_lo);
    cudaGetSymbolAddress((void**)&ath, g_at_hi);
    cudaGetSymbolAddress((void**)&atl, g_at_lo);
    cudaGetSymbolAddress((void**)&acth, g_act_hi);
    cudaGetSymbolAddress((void**)&actl, g_act_lo);
    cudaGetSymbolAddress((void**)&wqh, g_wqkv_hi);
    cudaGetSymbolAddress((void**)&wql, g_wqkv_lo);
    cudaGetSymbolAddress((void**)&waoh, g_wao_hi);
    cudaGetSymbolAddress((void**)&waol, g_wao_lo);
    cudaGetSymbolAddress((void**)&wfh, g_wfc_hi);
    cudaGetSymbolAddress((void**)&wfl, g_wfc_lo);
    cudaGetSymbolAddress((void**)&wph, g_wpo_hi);
    cudaGetSymbolAddress((void**)&wpl, g_wpo_lo);

    cudaFuncSetAttribute(attn_mma,     cudaFuncAttributeMaxDynamicSharedMemorySize, ATTN_SMEM);
    cudaFuncSetAttribute(hmma_gemm<0>, cudaFuncAttributeMaxDynamicSharedMemorySize, GEMM_SMEM);
    cudaFuncSetAttribute(hmma_gemm<1>, cudaFuncAttributeMaxDynamicSharedMemorySize, GEMM_SMEM);
    cudaFuncSetAttribute(hmma_gemm<2>, cudaFuncAttributeMaxDynamicSharedMemorySize, GEMM_SMEM);
    cudaFuncSetAttribute(hmma_gemm<3>, cudaFuncAttributeMaxDynamicSharedMemorySize, GEMM_SMEM);

    // fused weight conversion (single launch; every call, no caching)
    cvt_all_kernel<<<(N4_ALL + 255)/256, 256>>>(w_qkv, w_ao, w_fc, w_po);

    // 1. LN1 -> hi/lo
    ln_kernel<<<MM, 256>>>(x, ln1_g, ln1_b, lnh, lnl);
    // 2. QKV GEMM (M=4096, N=3072, K=1024), emit Q/K/V hi-lo [B,H,S,HD]
    hmma_gemm<0><<<dim3(3*EE/BN, MM/BM), GT, GEMM_SMEM>>>(
        lnh, lnl, wqh, wql, b_qkv, nullptr, nullptr, 3*EE, EE);
    // 3. HMMA causal flash attention -> at hi/lo
    attn_mma<<<dim3(SS/AQ, BB*HH), 256, ATTN_SMEM>>>(qh, ql, kh, kl, vh, vl, ath, atl);
    // 4. AO GEMM + residual -> x1 (fp32)
    hmma_gemm<1><<<dim3(EE/BN, MM/BM), GT, GEMM_SMEM>>>(
        ath, atl, waoh, waol, b_ao, x, x1, EE, EE);
    // 5. LN2 -> hi/lo
    ln_kernel<<<MM, 256>>>(x1, ln2_g, ln2_b, lnh, lnl);
    // 6. FC GEMM + gelu -> act hi/lo
    hmma_gemm<2><<<dim3(DFF/BN, MM/BM), GT, GEMM_SMEM>>>(
        lnh, lnl, wfh, wfl, b_fc, nullptr, nullptr, DFF, EE);
    // 7. PO GEMM + residual -> out
    hmma_gemm<3><<<dim3(EE/BN, MM/BM), GT, GEMM_SMEM>>>(
        acth, actl, wph, wpl, b_po, x1, out, EE, DFF);
}

// round 14
// speedup vs baseline: 1.0195x; 1.0195x over previous
#include <cuda_runtime.h>
#include <cuda_bf16.h>
#include <math.h>
#include <stdint.h>

// Problem constants
#define BB   2
#define SS   2048
#define EE   1024
#define HH   16
#define HD   64
#define DFF  4096
#define MM   (BB*SS)   // 4096 tokens

// ---------------- scratch (device globals; no allocations allowed) ----------
__device__ __align__(128) float g_x1[(size_t)MM*EE];     // residual after attn

__device__ __align__(128) __nv_bfloat16 g_qh [(size_t)MM*EE],  g_ql [(size_t)MM*EE];  // [B,H,S,HD]
__device__ __align__(128) __nv_bfloat16 g_kh [(size_t)MM*EE],  g_kl [(size_t)MM*EE];  // [B,H,S,HD]
__device__ __align__(128) __nv_bfloat16 g_vh [(size_t)MM*EE],  g_vl [(size_t)MM*EE];  // [B,H,S,HD]

__device__ __align__(128) __nv_bfloat16 g_ln_hi [(size_t)MM*EE],  g_ln_lo [(size_t)MM*EE];
__device__ __align__(128) __nv_bfloat16 g_at_hi [(size_t)MM*EE],  g_at_lo [(size_t)MM*EE];
__device__ __align__(128) __nv_bfloat16 g_act_hi[(size_t)MM*DFF], g_act_lo[(size_t)MM*DFF];

__device__ __align__(128) __nv_bfloat16 g_wqkv_hi[(size_t)3*EE*EE], g_wqkv_lo[(size_t)3*EE*EE];
__device__ __align__(128) __nv_bfloat16 g_wao_hi [(size_t)EE*EE],   g_wao_lo [(size_t)EE*EE];
__device__ __align__(128) __nv_bfloat16 g_wfc_hi [(size_t)DFF*EE],  g_wfc_lo [(size_t)DFF*EE];
__device__ __align__(128) __nv_bfloat16 g_wpo_hi [(size_t)EE*DFF],  g_wpo_lo [(size_t)EE*DFF];

// ---------------- helpers ----------------------------------------------------
__device__ __forceinline__ uint32_t smem_u32(const void* p) {
    uint32_t a;
    asm("{ .reg .u64 t; cvta.to.shared.u64 t, %1; cvt.u32.u64 %0, t; }"
        : "=r"(a) : "l"(p));
    return a;
}
__device__ __forceinline__ void cp16(uint32_t saddr, const void* gptr) {
    asm volatile("cp.async.cg.shared.global [%0], [%1], 16;"
                 :: "r"(saddr), "l"(gptr));
}
__device__ __forceinline__ void cp_commit() {
    asm volatile("cp.async.commit_group;" ::: "memory");
}
__device__ __forceinline__ void cp_wait0() {
    asm volatile("cp.async.wait_group 0;" ::: "memory");
}
__device__ __forceinline__ void ldsm4(uint32_t& r0, uint32_t& r1, uint32_t& r2,
                                      uint32_t& r3, uint32_t addr) {
    asm volatile("ldmatrix.sync.aligned.m8n8.x4.shared.b16 {%0,%1,%2,%3}, [%4];"
                 : "=r"(r0), "=r"(r1), "=r"(r2), "=r"(r3) : "r"(addr));
}
__device__ __forceinline__ void ldsm4t(uint32_t& r0, uint32_t& r1, uint32_t& r2,
                                       uint32_t& r3, uint32_t addr) {
    asm volatile("ldmatrix.sync.aligned.m8n8.x4.trans.shared.b16 {%0,%1,%2,%3}, [%4];"
                 : "=r"(r0), "=r"(r1), "=r"(r2), "=r"(r3) : "r"(addr));
}
__device__ __forceinline__ void mma16816(float* c, const uint32_t* a,
                                         uint32_t b0, uint32_t b1) {
    asm volatile(
        "mma.sync.aligned.m16n8k16.row.col.f32.bf16.bf16.f32 "
        "{%0,%1,%2,%3}, {%4,%5,%6,%7}, {%8,%9}, {%0,%1,%2,%3};"
        : "+f"(c[0]), "+f"(c[1]), "+f"(c[2]), "+f"(c[3])
        : "r"(a[0]), "r"(a[1]), "r"(a[2]), "r"(a[3]), "r"(b0), "r"(b1));
}

__device__ __forceinline__ float gelu_tanh(float x) {
    const float c = 0.7978845608028654f;
    return 0.5f * x * (1.0f + tanhf(c * (x + 0.044715f * x * x * x)));
}
__device__ __forceinline__ void split_bf16(float v, __nv_bfloat16& h, __nv_bfloat16& l) {
    h = __float2bfloat16(v);
    l = __float2bfloat16(v - __bfloat162float(h));
}
__device__ __forceinline__ uint32_t pack_bf16(__nv_bfloat16 a, __nv_bfloat16 b) {
    uint16_t ua = *reinterpret_cast<uint16_t*>(&a);
    uint16_t ub = *reinterpret_cast<uint16_t*>(&b);
    return (uint32_t)ua | ((uint32_t)ub << 16);
}

// ---------------- LayerNorm: row -> hi/lo bf16 -------------------------------
__global__ __launch_bounds__(256) void ln_kernel(
    const float* __restrict__ x, const float* __restrict__ g,
    const float* __restrict__ b, __nv_bfloat16* __restrict__ oh,
    __nv_bfloat16* __restrict__ ol)
{
    const int row = blockIdx.x;
    const int t   = threadIdx.x;
    const float4 v = ((const float4*)(x + (size_t)row * EE))[t];

    float s  = v.x + v.y + v.z + v.w;
    float ss = v.x*v.x + v.y*v.y + v.z*v.z + v.w*v.w;

    __shared__ float ws[8], wss[8];
    __shared__ float s_mu, s_rstd;
    const unsigned lane = t & 31u, w = t >> 5;
    #pragma unroll
    for (int off = 16; off; off >>= 1) {
        s  += __shfl_down_sync(0xffffffffu, s,  off);
        ss += __shfl_down_sync(0xffffffffu, ss, off);
    }
    if (lane == 0) { ws[w] = s; wss[w] = ss; }
    __syncthreads();
    if (t == 0) {
        float ts = 0.f, tss = 0.f;
        #pragma unroll
        for (int i = 0; i < 8; i++) { ts += ws[i]; tss += wss[i]; }
        const float mu  = ts * (1.0f / EE);
        const float var = tss * (1.0f / EE) - mu * mu;
        s_mu = mu; s_rstd = rsqrtf(var + 1e-5f);
    }
    __syncthreads();
    const float mu = s_mu, rstd = s_rstd;
    const float4 gg = ((const float4*)g)[t];
    const float4 bb = ((const float4*)b)[t];
    float o0 = (v.x - mu)*rstd*gg.x + bb.x;
    float o1 = (v.y - mu)*rstd*gg.y + bb.y;
    float o2 = (v.z - mu)*rstd*gg.z + bb.z;
    float o3 = (v.w - mu)*rstd*gg.w + bb.w;
    const size_t base = (size_t)row * EE + t * 4;
    __nv_bfloat16 h, l;
    split_bf16(o0, h, l); oh[base+0] = h; ol[base+0] = l;
    split_bf16(o1, h, l); oh[base+1] = h; ol[base+1] = l;
    split_bf16(o2, h, l); oh[base+2] = h; ol[base+2] = l;
    split_bf16(o3, h, l); oh[base+3] = h; ol[base+3] = l;
}

// ---------------- fused weight fp32 -> hi/lo bf16 (all 4 weights) ------------
#define N4_QKV  (3*EE*EE/4)
#define N4_AO   (EE*EE/4)
#define N4_FC   (DFF*EE/4)
#define N4_PO   (EE*DFF/4)
#define N4_ALL  (N4_QKV + N4_AO + N4_FC + N4_PO)

__global__ __launch_bounds__(256) void cvt_all_kernel(
    const float* __restrict__ s_qkv, const float* __restrict__ s_ao,
    const float* __restrict__ s_fc,  const float* __restrict__ s_po)
{
    int i = blockIdx.x * 256 + threadIdx.x;
    if (i >= N4_ALL) return;
    const float* src;
    __nv_bfloat16 *hi, *lo;
    if (i < N4_QKV)                      { src = s_qkv; hi = g_wqkv_hi; lo = g_wqkv_lo; }
    else if (i < N4_QKV + N4_AO)         { i -= N4_QKV; src = s_ao; hi = g_wao_hi; lo = g_wao_lo; }
    else if (i < N4_QKV + N4_AO + N4_FC) { i -= N4_QKV + N4_AO; src = s_fc; hi = g_wfc_hi; lo = g_wfc_lo; }
    else                                 { i -= N4_QKV + N4_AO + N4_FC; src = s_po; hi = g_wpo_hi; lo = g_wpo_lo; }
    const float4 v = ((const float4*)src)[i];
    __nv_bfloat16 h, l;
    const size_t base = (size_t)i * 4;
    split_bf16(v.x, h, l); hi[base+0] = h; lo[base+0] = l;
    split_bf16(v.y, h, l); hi[base+1] = h; lo[base+1] = l;
    split_bf16(v.z, h, l); hi[base+2] = h; lo[base+2] = l;
    split_bf16(v.w, h, l); hi[base+3] = h; lo[base+3] = l;
}

// ---------------- HMMA bf16x3 GEMM -------------------------------------------
// C[M,N] = A[M,K] @ W[N,K]^T via AhBh + AhBl + AlBh.
// 256x128 block tile (weight-traffic-optimal), BK=64, 256 threads = 8 warps
// (4m x 2n of 64x64), 2-stage cp.async, single sync per chunk.
// Stage: A hi/lo 32K+32K | B hi/lo 16K+16K = 96K; x2 = 192K smem.
#define BM 256
#define BN 128
#define BK 64
#define GT 256
#define STAGE_BYTES 98304
#define SOFF_B 65536
#define GEMM_SMEM (2*STAGE_BYTES) // 196608

template<int MODE>
__global__ __launch_bounds__(GT, 1)
void hmma_gemm(const __nv_bfloat16* __restrict__ Ah, const __nv_bfloat16* __restrict__ Al,
               const __nv_bfloat16* __restrict__ Wh, const __nv_bfloat16* __restrict__ Wl,
               const float* __restrict__ bias, const float* __restrict__ res,
               float* __restrict__ out, int N, int K)
{
    extern __shared__ char smem[];
    const uint32_t sb = smem_u32(smem);
    const int tid  = threadIdx.x;
    const int wid  = tid >> 5;
    const int lane = tid & 31;
    const int m0 = blockIdx.y * BM, n0 = blockIdx.x * BN;
    const int warp_m0 = (wid & 3) * 64;   // 4 warps along m (64 rows)
    const int warp_n0 = (wid >> 2) * 64;  // 2 warps along n (64 cols)

    const int nch = K / BK;

    // per stage: 6144 x 16B units: A hi/lo (2048 each), B hi/lo (1024 each)
    auto load_chunk = [&](int stage, int k0) {
        #pragma unroll
        for (int qq = 0; qq < 24; qq++) {
            const int it = tid + qq * GT;       // 0..6143
            uint32_t soff;
            const __nv_bfloat16* gp;
            if (it < 4096) {                    // A (256 rows x 64)
                const int hl  = it >> 11;
                const int idx = it & 2047;
                const int r   = idx >> 3;       // 0..255
                const int u   = idx & 7;
                gp = (hl ? Al : Ah) + (size_t)(m0 + r) * K + k0 + u * 8;
                soff = stage * STAGE_BYTES + hl * 32768 + r * 128 +
                       ((u ^ (r & 7)) * 16);
            } else {                            // B (128 rows x 64)
                const int it2 = it - 4096;
                const int hl  = it2 >> 10;
                const int idx = it2 & 1023;
                const int r   = idx >> 3;       // 0..127
                const int u   = idx & 7;
                gp = (hl ? Wl : Wh) + (size_t)(n0 + r) * K + k0 + u * 8;
                soff = stage * STAGE_BYTES + SOFF_B + hl * 16384 + r * 128 +
                       ((u ^ (r & 7)) * 16);
            }
            cp16(sb + soff, gp);
        }
    };

    float acc[4][8][4];
    #pragma unroll
    for (int i = 0; i < 4; i++)
        #pragma unroll
        for (int j = 0; j < 8; j++)
            #pragma unroll
            for (int e = 0; e < 4; e++) acc[i][j][e] = 0.f;

    load_chunk(0, 0);   cp_commit();

    const int g  = lane >> 3;
    const int tg = lane & 7;
    const int rowA_off = (g & 1) * 8 + tg;
    const int rowB_off = (g >> 1) * 8 + tg;

    for (int c = 0; c < nch; c++) {
        cp_wait0();          // chunk c resident (only group in flight)
        __syncthreads();     // all warps done with buf (c+1)&1 (chunk c-1)
        if (c + 1 < nch) load_chunk((c + 1) & 1, (c + 1) * BK);
        cp_commit();         // loads for c+1 overlap compute of c

        const uint32_t stA = sb + (c & 1) * STAGE_BYTES;
        const uint32_t stB = stA + SOFF_B;

        #pragma unroll
        for (int kk = 0; kk < 4; kk++) {
            uint32_t ah[4][4], al[4][4];
            const int unitA = kk * 2 + (g >> 1);
            #pragma unroll
            for (int tm = 0; tm < 4; tm++) {
                const int r = warp_m0 + tm * 16 + rowA_off;
                const uint32_t a = stA + r * 128 + ((unitA ^ (r & 7)) * 16);
                ldsm4(ah[tm][0], ah[tm][1], ah[tm][2], ah[tm][3], a);
                ldsm4(al[tm][0], al[tm][1], al[tm][2], al[tm][3], a + 32768);
            }
            const int unitB = kk * 2 + (g & 1);
            #pragma unroll
            for (int bn = 0; bn < 4; bn++) {
                const int r = warp_n0 + bn * 16 + rowB_off;
                const uint32_t a = stB + r * 128 + ((unitB ^ (r & 7)) * 16);
                uint32_t bh[4], bl[4];
                ldsm4(bh[0], bh[1], bh[2], bh[3], a);
                ldsm4(bl[0], bl[1], bl[2], bl[3], a + 16384);
                #pragma unroll
                for (int tm = 0; tm < 4; tm++) {
                    mma16816(acc[tm][2*bn],   ah[tm], bh[0], bh[1]);
                    mma16816(acc[tm][2*bn],   ah[tm], bl[0], bl[1]);
                    mma16816(acc[tm][2*bn],   al[tm], bh[0], bh[1]);
                    mma16816(acc[tm][2*bn+1], ah[tm], bh[2], bh[3]);
                    mma16816(acc[tm][2*bn+1], ah[tm], bl[2], bl[3]);
                    mma16816(acc[tm][2*bn+1], al[tm], bh[2], bh[3]);
                }
            }
        }
    }

    // ---- epilogue ----
    const int r_lo = lane >> 2;
    const int c_lo = (lane & 3) * 2;
    #pragma unroll
    for (int tm = 0; tm < 4; tm++) {
        #pragma unroll
        for (int tn = 0; tn < 8; tn++) {
            const int n = n0 + warp_n0 + tn * 8 + c_lo;
            #pragma unroll
            for (int h = 0; h < 2; h++) {
                const int m = m0 + warp_m0 + tm * 16 + r_lo + h * 8;
                float v0 = acc[tm][tn][h * 2 + 0] + bias[n];
                float v1 = acc[tm][tn][h * 2 + 1] + bias[n + 1];
                if (MODE == 0) {
                    // all of Q/K/V stored hi-lo [B,H,S,HD] (packed stores)
                    const int head  = n / (3 * HD);
                    const int rem   = n % (3 * HD);
                    const int which = rem / HD;
                    const int d     = rem % HD;      // even
                    const int bI    = m / SS;
                    const int sI    = m % SS;
                    __nv_bfloat16 h0, l0, h1, l1;
                    split_bf16(v0, h0, l0);
                    split_bf16(v1, h1, l1);
                    const size_t dst = (((size_t)bI * HH + head) * SS + sI) * HD + d;
                    __nv_bfloat16* ph = (which == 0) ? g_qh : (which == 1) ? g_kh : g_vh;
                    __nv_bfloat16* pl = (which == 0) ? g_ql : (which == 1) ? g_kl : g_vl;
                    *(uint32_t*)(ph + dst) = pack_bf16(h0, h1);
                    *(uint32_t*)(pl + dst) = pack_bf16(l0, l1);
                } else if (MODE == 1 || MODE == 3) {
                    const size_t o = (size_t)m * N + n;
                    const float2 rr = *(const float2*)(res + o);
                    float2 ov; ov.x = v0 + rr.x; ov.y = v1 + rr.y;
                    *(float2*)(out + o) = ov;
                } else { // MODE 2: gelu -> hi/lo bf16
                    const size_t o = (size_t)m * N + n;
                    __nv_bfloat16 hh, ll;
                    float gv0 = gelu_tanh(v0), gv1 = gelu_tanh(v1);
                    split_bf16(gv0, hh, ll); g_act_hi[o]   = hh; g_act_lo[o]   = ll;
                    split_bf16(gv1, hh, ll); g_act_hi[o+1] = hh; g_act_lo[o+1] = ll;
                }
            }
        }
    }
}

// ---------------- HMMA flash attention (causal) ------------------------------
// Block: 128 queries, 8 warps (16 rows each), kv tiles of 64, double-buffered,
// single sync per tile. Q/K/V all hi-lo [B,H,S,HD]. V frags via ldmatrix.trans.
#define AQ  128
#define AKV 64
#define SQ_H 0
#define SQ_L 16384
#define SST(s) (32768 + (s)*32768)
#define SV_OFF 16384   // K at 0/8192 hi/lo, V at 16384/24576
#define ATTN_SMEM 98304

__global__ __launch_bounds__(256, 1) void attn_mma(
    const __nv_bfloat16* __restrict__ Qh, const __nv_bfloat16* __restrict__ Ql,
    const __nv_bfloat16* __restrict__ Kh, const __nv_bfloat16* __restrict__ Kl,
    const __nv_bfloat16* __restrict__ Vh, const __nv_bfloat16* __restrict__ Vl,
    __nv_bfloat16* __restrict__ Oh, __nv_bfloat16* __restrict__ Ol)
{
    extern __shared__ char smem[];
    const uint32_t sb = smem_u32(smem);
    const int tid  = threadIdx.x;
    const int wid  = tid >> 5;
    const int lane = tid & 31;
    const int bh   = blockIdx.y;
    const int q0   = blockIdx.x * AQ;
    const int g  = lane >> 3;
    const int tg = lane & 7;

    const __nv_bfloat16* Qhb = Qh + (size_t)bh * SS * HD;
    const __nv_bfloat16* Qlb = Ql + (size_t)bh * SS * HD;
    const __nv_bfloat16* Khb = Kh + (size_t)bh * SS * HD;
    const __nv_bfloat16* Klb = Kl + (size_t)bh * SS * HD;
    const __nv_bfloat16* Vhb = Vh + (size_t)bh * SS * HD;
    const __nv_bfloat16* Vlb = Vl + (size_t)bh * SS * HD;

    // ---- Q tile load (hi/lo, 128x64, swizzled) ----
    #pragma unroll
    for (int qq = 0; qq < 8; qq++) {
        const int it = tid + qq * 256;     // 0..2047
        const int hl = it >> 10;
        const int r  = (it >> 3) & 127;
        const int u  = it & 7;
        const __nv_bfloat16* src = (hl ? Qlb : Qhb) + (size_t)(q0 + r) * HD + u * 8;
        cp16(sb + (hl ? SQ_L : SQ_H) + r * 128 + ((u ^ (r & 7)) * 16), src);
    }

    const int nkv = 2 * blockIdx.x + 2;

    auto load_kv = [&](int stage, int kv0) {
        #pragma unroll
        for (int qq = 0; qq < 8; qq++) {
            const int it  = tid + qq * 256;
            const int mat = it >> 9;          // 0 Kh, 1 Kl, 2 Vh, 3 Vl
            const int r   = (it >> 3) & 63;
            const int u   = it & 7;
            const __nv_bfloat16* src;
            if (mat == 0)      src = Khb + (size_t)(kv0 + r) * HD + u * 8;
            else if (mat == 1) src = Klb + (size_t)(kv0 + r) * HD + u * 8;
            else if (mat == 2) src = Vhb + (size_t)(kv0 + r) * HD + u * 8;
            else               src = Vlb + (size_t)(kv0 + r) * HD + u * 8;
            cp16(sb + SST(stage) + mat * 8192 + r * 128 + ((u ^ (r & 7)) * 16), src);
        }
    };

    load_kv(0, 0);
    cp_commit();        // single group: Q + kv0
    cp_wait0();
    __syncthreads();

    // ---- Q fragments to registers (Q region never overwritten) ----
    uint32_t qfh[4][4], qfl[4][4];
    const int rowA_off = (g & 1) * 8 + tg;
    {
        #pragma unroll
        for (int t = 0; t < 4; t++) {
            const int r  = wid * 16 + rowA_off;
            const int uA = t * 2 + (g >> 1);
            const uint32_t a = sb + SQ_H + r * 128 + ((uA ^ (r & 7)) * 16);
            ldsm4(qfh[t][0], qfh[t][1], qfh[t][2], qfh[t][3], a);
            ldsm4(qfl[t][0], qfl[t][1], qfl[t][2], qfl[t][3], a + 16384);
        }
    }

    float m_i[2] = {-1e30f, -1e30f};
    float l_i[2] = {0.f, 0.f};
    float acc_o[8][4];
    #pragma unroll
    for (int nt = 0; nt < 8; nt++)
        #pragma unroll
        for (int e = 0; e < 4; e++) acc_o[nt][e] = 0.f;

    const int rowB_off = (g >> 1) * 8 + tg;

    for (int j = 0; j < nkv; j++) {
        const int kv0 = j * AKV;
        if (j > 0) { cp_wait0(); __syncthreads(); }
        if (j + 1 < nkv) { load_kv((j + 1) & 1, (j + 1) * AKV); cp_commit(); }

        const uint32_t st = sb + SST(j & 1);

        // ---- S = Q K^T (3-pass hi/lo) ----
        float accs[8][4];
        #pragma unroll
        for (int nt = 0; nt < 8; nt++)
            #pragma unroll
            for (int e = 0; e < 4; e++) accs[nt][e] = 0.f;

        #pragma unroll
        for (int t = 0; t < 4; t++) {
            const int uB = t * 2 + (g & 1);
            #pragma unroll
            for (int bn = 0; bn < 4; bn++) {
                const int r = bn * 16 + rowB_off;
                const uint32_t a = st + r * 128 + ((uB ^ (r & 7)) * 16);
                uint32_t kbh[4], kbl[4];
                ldsm4(kbh[0], kbh[1], kbh[2], kbh[3], a);
                ldsm4(kbl[0], kbl[1], kbl[2], kbl[3], a + 8192);
                mma16816(accs[2*bn],   qfh[t], kbh[0], kbh[1]);
                mma16816(accs[2*bn],   qfh[t], kbl[0], kbl[1]);
                mma16816(accs[2*bn],   qfl[t], kbh[0], kbh[1]);
                mma16816(accs[2*bn+1], qfh[t], kbh[2], kbh[3]);
                mma16816(accs[2*bn+1], qfh[t], kbl[2], kbl[3]);
                mma16816(accs[2*bn+1], qfl[t], kbh[2], kbh[3]);
            }
        }
        #pragma unroll
        for (int nt = 0; nt < 8; nt++)
            #pragma unroll
            for (int e = 0; e < 4; e++) accs[nt][e] *= 0.125f;

        // ---- causal mask (only on near-diagonal tiles for this warp) ----
        if (kv0 + AKV - 1 > q0 + wid * 16) {
            #pragma unroll
            for (int nt = 0; nt < 8; nt++)
                #pragma unroll
                for (int e = 0; e < 4; e++) {
                    const int row = q0 + wid * 16 + (lane >> 2) + ((e >> 1) ? 8 : 0);
                    const int col = kv0 + nt * 8 + 2 * (lane & 3) + (e & 1);
                    if (col > row) accs[nt][e] = -1e30f;
                }
        }

        // ---- online softmax (rows r and r+8 per thread) ----
        #pragma unroll
        for (int h = 0; h < 2; h++) {
            float rm = -1e30f;
            #pragma unroll
            for (int nt = 0; nt < 8; nt++)
                rm = fmaxf(rm, fmaxf(accs[nt][2*h], accs[nt][2*h+1]));
            rm = fmaxf(rm, __shfl_xor_sync(0xffffffffu, rm, 1));
            rm = fmaxf(rm, __shfl_xor_sync(0xffffffffu, rm, 2));
            const float mnew = fmaxf(m_i[h], rm);
            const float corr = __expf(m_i[h] - mnew);
            m_i[h] = mnew;
            float rs = 0.f;
            #pragma unroll
            for (int nt = 0; nt < 8; nt++) {
                accs[nt][2*h]   = __expf(accs[nt][2*h]   - mnew);
                accs[nt][2*h+1] = __expf(accs[nt][2*h+1] - mnew);
                rs += accs[nt][2*h] + accs[nt][2*h+1];
            }
            rs += __shfl_xor_sync(0xffffffffu, rs, 1);
            rs += __shfl_xor_sync(0xffffffffu, rs, 2);
            l_i[h] = l_i[h] * corr + rs;
            #pragma unroll
            for (int nt = 0; nt < 8; nt++) {
                acc_o[nt][2*h]   *= corr;
                acc_o[nt][2*h+1] *= corr;
            }
        }

        // ---- pack P to hi/lo A-fragments ----
        uint32_t pfh[4][4], pfl[4][4];
        #pragma unroll
        for (int t = 0; t < 4; t++) {
            #pragma unroll
            for (int half = 0; half < 2; half++) {
                const int nt = 2 * t + half;
                __nv_bfloat16 h0, l0, h1, l1, h2, l2, h3, l3;
                split_bf16(accs[nt][0], h0, l0);
                split_bf16(accs[nt][1], h1, l1);
                split_bf16(accs[nt][2], h2, l2);
                split_bf16(accs[nt][3], h3, l3);
                pfh[t][half*2+0] = pack_bf16(h0, h1);
                pfh[t][half*2+1] = pack_bf16(h2, h3);
                pfl[t][half*2+0] = pack_bf16(l0, l1);
                pfl[t][half*2+1] = pack_bf16(l2, l3);
            }
        }

        // ---- O += P V (3-pass hi/lo). V tile [kv][d]; B-frags via ldsm.trans ----
        #pragma unroll
        for (int t = 0; t < 4; t++) {
            #pragma unroll
            for (int bn = 0; bn < 4; bn++) {
                const int r = t * 16 + rowA_off;             // kv row
                const int u = bn * 2 + (g >> 1);             // d unit
                const uint32_t a = st + SV_OFF + r * 128 + ((u ^ (r & 7)) * 16);
                uint32_t vbh[4], vbl[4];
                ldsm4t(vbh[0], vbh[1], vbh[2], vbh[3], a);
                ldsm4t(vbl[0], vbl[1], vbl[2], vbl[3], a + 8192);
                mma16816(acc_o[2*bn],   pfh[t], vbh[0], vbh[1]);
                mma16816(acc_o[2*bn],   pfh[t], vbl[0], vbl[1]);
                mma16816(acc_o[2*bn],   pfl[t], vbh[0], vbh[1]);
                mma16816(acc_o[2*bn+1], pfh[t], vbh[2], vbh[3]);
                mma16816(acc_o[2*bn+1], pfh[t], vbl[2], vbl[3]);
                mma16816(acc_o[2*bn+1], pfl[t], vbh[2], vbh[3]);
            }
        }
    }

    // ---- epilogue: O / l_i -> at hi/lo [B,S,E] ----
    const int bI = bh / HH;
    const int hI = bh % HH;
    #pragma unroll
    for (int h = 0; h < 2; h++) {
        const float inv = 1.0f / l_i[h];
        const int sI = q0 + wid * 16 + (lane >> 2) + h * 8;
        const size_t base = ((size_t)bI * SS + sI) * EE + hI * HD;
        #pragma unroll
        for (int nt = 0; nt < 8; nt++) {
            const int d = nt * 8 + 2 * (lane & 3);
            __nv_bfloat16 h0, l0, h1, l1;
            split_bf16(acc_o[nt][2*h]   * inv, h0, l0);
            split_bf16(acc_o[nt][2*h+1] * inv, h1, l1);
            *(uint32_t*)(Oh + base + d) = pack_bf16(h0, h1);
            *(uint32_t*)(Ol + base + d) = pack_bf16(l0, l1);
        }
    }
}

// ---------------- launch ----------------------------------------------------
extern "C" void kernel_launch(void* const* d_in, const int* in_sizes, int n_in,
                              void* d_out, int out_size)
{
    const float* x     = (const float*)d_in[0];
    const float* ln1_g = (const float*)d_in[1];
    const float* ln1_b = (const float*)d_in[2];
    const float* ln2_g = (const float*)d_in[3];
    const float* ln2_b = (const float*)d_in[4];
    const float* w_qkv = (const float*)d_in[5];
    const float* b_qkv = (const float*)d_in[6];
    const float* w_ao  = (const float*)d_in[7];
    const float* b_ao  = (const float*)d_in[8];
    const float* w_fc  = (const float*)d_in[9];
    const float* b_fc  = (const float*)d_in[10];
    const float* w_po  = (const float*)d_in[11];
    const float* b_po  = (const float*)d_in[12];
    float* out = (float*)d_out;

    float *x1;
    __nv_bfloat16 *qh, *ql, *kh, *kl, *vh, *vl;
    __nv_bfloat16 *lnh, *lnl, *ath, *atl, *acth, *actl;
    __nv_bfloat16 *wqh, *wql, *waoh, *waol, *wfh, *wfl, *wph, *wpl;
    cudaGetSymbolAddress((void**)&x1,  g_x1);
    cudaGetSymbolAddress((void**)&qh,  g_qh);
    cudaGetSymbolAddress((void**)&ql,  g_ql);
    cudaGetSymbolAddress((void**)&kh,  g_kh);
    cudaGetSymbolAddress((void**)&kl,  g_kl);
    cudaGetSymbolAddress((void**)&vh,  g_vh);
    cudaGetSymbolAddress((void**)&vl,  g_vl);
    cudaGetSymbolAddress((void**)&lnh, g_ln_hi);
    cudaGetSymbolAddress((void**)&lnl, g_ln_lo);
    cudaGetSymbolAddress((void**)&ath, g_at_hi);
    cudaGetSymbolAddress((void**)&atl, g_at_lo);
    cudaGetSymbolAddress((void**)&acth, g_act_hi);
    cudaGetSymbolAddress((void**)&actl, g_act_lo);
    cudaGetSymbolAddress((void**)&wqh, g_wqkv_hi);
    cudaGetSymbolAddress((void**)&wql, g_wqkv_lo);
    cudaGetSymbolAddress((void**)&waoh, g_wao_hi);
    cudaGetSymbolAddress((void**)&waol, g_wao_lo);
    cudaGetSymbolAddress((void**)&wfh, g_wfc_hi);
    cudaGetSymbolAddress((void**)&wfl, g_wfc_lo);
    cudaGetSymbolAddress((void**)&wph, g_wpo_hi);
    cudaGetSymbolAddress((void**)&wpl, g_wpo_lo);

    cudaFuncSetAttribute(attn_mma,     cudaFuncAttributeMaxDynamicSharedMemorySize, ATTN_SMEM);
    cudaFuncSetAttribute(hmma_gemm<0>, cudaFuncAttributeMaxDynamicSharedMemorySize, GEMM_SMEM);
    cudaFuncSetAttribute(hmma_gemm<1>, cudaFuncAttributeMaxDynamicSharedMemorySize, GEMM_SMEM);
    cudaFuncSetAttribute(hmma_gemm<2>, cudaFuncAttributeMaxDynamicSharedMemorySize, GEMM_SMEM);
    cudaFuncSetAttribute(hmma_gemm<3>, cudaFuncAttributeMaxDynamicSharedMemorySize, GEMM_SMEM);

    // fused weight conversion (single launch; every call, no caching)
    cvt_all_kernel<<<(N4_ALL + 255)/256, 256>>>(w_qkv, w_ao, w_fc, w_po);

    // 1. LN1 -> hi/lo
    ln_kernel<<<MM, 256>>>(x, ln1_g, ln1_b, lnh, lnl);
    // 2. QKV GEMM (M=4096, N=3072, K=1024), emit Q/K/V hi-lo [B,H,S,HD]
    hmma_gemm<0><<<dim3(3*EE/BN, MM/BM), GT, GEMM_SMEM>>>(
        lnh, lnl, wqh, wql, b_qkv, nullptr, nullptr, 3*EE, EE);
    // 3. HMMA causal flash attention -> at hi/lo
    attn_mma<<<dim3(SS/AQ, BB*HH), 256, ATTN_SMEM>>>(qh, ql, kh, kl, vh, vl, ath, atl);
    // 4. AO GEMM + residual -> x1 (fp32)
    hmma_gemm<1><<<dim3(EE/BN, MM/BM), GT, GEMM_SMEM>>>(
        ath, atl, waoh, waol, b_ao, x, x1, EE, EE);
    // 5. LN2 -> hi/lo
    ln_kernel<<<MM, 256>>>(x1, ln2_g, ln2_b, lnh, lnl);
    // 6. FC GEMM + gelu -> act hi/lo
    hmma_gemm<2><<<dim3(DFF/BN, MM/BM), GT, GEMM_SMEM>>>(
        lnh, lnl, wfh, wfl, b_fc, nullptr, nullptr, DFF, EE);
    // 7. PO GEMM + residual -> out
    hmma_gemm<3><<<dim3(EE/BN, MM/BM), GT, GEMM_SMEM>>>(
        acth, actl, wph, wpl, b_po, x1, out, EE, DFF);
}

// round 15
// speedup vs baseline: 1.0288x; 1.0092x over previous
#include <cuda_runtime.h>
#include <cuda_bf16.h>
#include <math.h>
#include <stdint.h>

// Problem constants
#define BB   2
#define SS   2048
#define EE   1024
#define HH   16
#define HD   64
#define DFF  4096
#define MM   (BB*SS)   // 4096 tokens

// ---------------- scratch (device globals; no allocations allowed) ----------
__device__ __align__(128) float g_x1[(size_t)MM*EE];     // residual after attn

__device__ __align__(128) __nv_bfloat16 g_qh [(size_t)MM*EE],  g_ql [(size_t)MM*EE];  // [B,H,S,HD]
__device__ __align__(128) __nv_bfloat16 g_kh [(size_t)MM*EE],  g_kl [(size_t)MM*EE];  // [B,H,S,HD]
__device__ __align__(128) __nv_bfloat16 g_vh [(size_t)MM*EE],  g_vl [(size_t)MM*EE];  // [B,H,S,HD]

__device__ __align__(128) __nv_bfloat16 g_ln_hi [(size_t)MM*EE],  g_ln_lo [(size_t)MM*EE];
__device__ __align__(128) __nv_bfloat16 g_at_hi [(size_t)MM*EE],  g_at_lo [(size_t)MM*EE];
__device__ __align__(128) __nv_bfloat16 g_act_hi[(size_t)MM*DFF], g_act_lo[(size_t)MM*DFF];

__device__ __align__(128) __nv_bfloat16 g_wqkv_hi[(size_t)3*EE*EE], g_wqkv_lo[(size_t)3*EE*EE];
__device__ __align__(128) __nv_bfloat16 g_wao_hi [(size_t)EE*EE],   g_wao_lo [(size_t)EE*EE];
__device__ __align__(128) __nv_bfloat16 g_wfc_hi [(size_t)DFF*EE],  g_wfc_lo [(size_t)DFF*EE];
__device__ __align__(128) __nv_bfloat16 g_wpo_hi [(size_t)EE*DFF],  g_wpo_lo [(size_t)EE*DFF];

// ---------------- helpers ----------------------------------------------------
__device__ __forceinline__ uint32_t smem_u32(const void* p) {
    uint32_t a;
    asm("{ .reg .u64 t; cvta.to.shared.u64 t, %1; cvt.u32.u64 %0, t; }"
        : "=r"(a) : "l"(p));
    return a;
}
__device__ __forceinline__ void cp16(uint32_t saddr, const void* gptr) {
    asm volatile("cp.async.cg.shared.global [%0], [%1], 16;"
                 :: "r"(saddr), "l"(gptr));
}
__device__ __forceinline__ void cp_commit() {
    asm volatile("cp.async.commit_group;" ::: "memory");
}
__device__ __forceinline__ void cp_wait0() {
    asm volatile("cp.async.wait_group 0;" ::: "memory");
}
__device__ __forceinline__ void ldsm4(uint32_t& r0, uint32_t& r1, uint32_t& r2,
                                      uint32_t& r3, uint32_t addr) {
    asm volatile("ldmatrix.sync.aligned.m8n8.x4.shared.b16 {%0,%1,%2,%3}, [%4];"
                 : "=r"(r0), "=r"(r1), "=r"(r2), "=r"(r3) : "r"(addr));
}
__device__ __forceinline__ void ldsm4t(uint32_t& r0, uint32_t& r1, uint32_t& r2,
                                       uint32_t& r3, uint32_t addr) {
    asm volatile("ldmatrix.sync.aligned.m8n8.x4.trans.shared.b16 {%0,%1,%2,%3}, [%4];"
                 : "=r"(r0), "=r"(r1), "=r"(r2), "=r"(r3) : "r"(addr));
}
__device__ __forceinline__ void mma16816(float* c, const uint32_t* a,
                                         uint32_t b0, uint32_t b1) {
    asm volatile(
        "mma.sync.aligned.m16n8k16.row.col.f32.bf16.bf16.f32 "
        "{%0,%1,%2,%3}, {%4,%5,%6,%7}, {%8,%9}, {%0,%1,%2,%3};"
        : "+f"(c[0]), "+f"(c[1]), "+f"(c[2]), "+f"(c[3])
        : "r"(a[0]), "r"(a[1]), "r"(a[2]), "r"(a[3]), "r"(b0), "r"(b1));
}

__device__ __forceinline__ float gelu_tanh(float x) {
    const float c = 0.7978845608028654f;
    return 0.5f * x * (1.0f + tanhf(c * (x + 0.044715f * x * x * x)));
}
__device__ __forceinline__ void split_bf16(float v, __nv_bfloat16& h, __nv_bfloat16& l) {
    h = __float2bfloat16(v);
    l = __float2bfloat16(v - __bfloat162float(h));
}
__device__ __forceinline__ uint32_t pack_bf16(__nv_bfloat16 a, __nv_bfloat16 b) {
    uint16_t ua = *reinterpret_cast<uint16_t*>(&a);
    uint16_t ub = *reinterpret_cast<uint16_t*>(&b);
    return (uint32_t)ua | ((uint32_t)ub << 16);
}

// ---------------- LayerNorm row body (shared by ln_kernel & fused cvt) -------
__device__ __forceinline__ void ln_row(
    const float* __restrict__ x, const float* __restrict__ g,
    const float* __restrict__ b, __nv_bfloat16* __restrict__ oh,
    __nv_bfloat16* __restrict__ ol, int row)
{
    const int t = threadIdx.x;
    const float4 v = ((const float4*)(x + (size_t)row * EE))[t];

    float s  = v.x + v.y + v.z + v.w;
    float ss = v.x*v.x + v.y*v.y + v.z*v.z + v.w*v.w;

    __shared__ float ws[8], wss[8];
    __shared__ float s_mu, s_rstd;
    const unsigned lane = t & 31u, w = t >> 5;
    #pragma unroll
    for (int off = 16; off; off >>= 1) {
        s  += __shfl_down_sync(0xffffffffu, s,  off);
        ss += __shfl_down_sync(0xffffffffu, ss, off);
    }
    if (lane == 0) { ws[w] = s; wss[w] = ss; }
    __syncthreads();
    if (t == 0) {
        float ts = 0.f, tss = 0.f;
        #pragma unroll
        for (int i = 0; i < 8; i++) { ts += ws[i]; tss += wss[i]; }
        const float mu  = ts * (1.0f / EE);
        const float var = tss * (1.0f / EE) - mu * mu;
        s_mu = mu; s_rstd = rsqrtf(var + 1e-5f);
    }
    __syncthreads();
    const float mu = s_mu, rstd = s_rstd;
    const float4 gg = ((const float4*)g)[t];
    const float4 bb = ((const float4*)b)[t];
    float o0 = (v.x - mu)*rstd*gg.x + bb.x;
    float o1 = (v.y - mu)*rstd*gg.y + bb.y;
    float o2 = (v.z - mu)*rstd*gg.z + bb.z;
    float o3 = (v.w - mu)*rstd*gg.w + bb.w;
    const size_t base = (size_t)row * EE + t * 4;
    __nv_bfloat16 h, l;
    split_bf16(o0, h, l); oh[base+0] = h; ol[base+0] = l;
    split_bf16(o1, h, l); oh[base+1] = h; ol[base+1] = l;
    split_bf16(o2, h, l); oh[base+2] = h; ol[base+2] = l;
    split_bf16(o3, h, l); oh[base+3] = h; ol[base+3] = l;
}

__global__ __launch_bounds__(256) void ln_kernel(
    const float* __restrict__ x, const float* __restrict__ g,
    const float* __restrict__ b, __nv_bfloat16* __restrict__ oh,
    __nv_bfloat16* __restrict__ ol)
{
    ln_row(x, g, b, oh, ol, blockIdx.x);
}

// ---------------- fused weight cvt + LN1 (single launch) ---------------------
#define N4_QKV  (3*EE*EE/4)
#define N4_AO   (EE*EE/4)
#define N4_FC   (DFF*EE/4)
#define N4_PO   (EE*DFF/4)
#define N4_ALL  (N4_QKV + N4_AO + N4_FC + N4_PO)
#define CVT_BLOCKS ((N4_ALL + 255) / 256)

__global__ __launch_bounds__(256) void cvt_ln1_kernel(
    const float* __restrict__ s_qkv, const float* __restrict__ s_ao,
    const float* __restrict__ s_fc,  const float* __restrict__ s_po,
    const float* __restrict__ x, const float* __restrict__ ln1_g,
    const float* __restrict__ ln1_b)
{
    if (blockIdx.x >= CVT_BLOCKS) {
        ln_row(x, ln1_g, ln1_b, g_ln_hi, g_ln_lo, blockIdx.x - CVT_BLOCKS);
        return;
    }
    int i = blockIdx.x * 256 + threadIdx.x;
    if (i >= N4_ALL) return;
    const float* src;
    __nv_bfloat16 *hi, *lo;
    if (i < N4_QKV)                      { src = s_qkv; hi = g_wqkv_hi; lo = g_wqkv_lo; }
    else if (i < N4_QKV + N4_AO)         { i -= N4_QKV; src = s_ao; hi = g_wao_hi; lo = g_wao_lo; }
    else if (i < N4_QKV + N4_AO + N4_FC) { i -= N4_QKV + N4_AO; src = s_fc; hi = g_wfc_hi; lo = g_wfc_lo; }
    else                                 { i -= N4_QKV + N4_AO + N4_FC; src = s_po; hi = g_wpo_hi; lo = g_wpo_lo; }
    const float4 v = ((const float4*)src)[i];
    __nv_bfloat16 h, l;
    const size_t base = (size_t)i * 4;
    split_bf16(v.x, h, l); hi[base+0] = h; lo[base+0] = l;
    split_bf16(v.y, h, l); hi[base+1] = h; lo[base+1] = l;
    split_bf16(v.z, h, l); hi[base+2] = h; lo[base+2] = l;
    split_bf16(v.w, h, l); hi[base+3] = h; lo[base+3] = l;
}

// ---------------- HMMA bf16x3 GEMM -------------------------------------------
// C[M,N] = A[M,K] @ W[N,K]^T via AhBh + AhBl + AlBh.
// 256x128 block tile, BK=64, 256 threads = 8 warps (4m x 2n of 64x64),
// 2-stage cp.async, single sync per chunk.
#define BM 256
#define BN 128
#define BK 64
#define GT 256
#define STAGE_BYTES 98304
#define SOFF_B 65536
#define GEMM_SMEM (2*STAGE_BYTES) // 196608

template<int MODE>
__global__ __launch_bounds__(GT, 1)
void hmma_gemm(const __nv_bfloat16* __restrict__ Ah, const __nv_bfloat16* __restrict__ Al,
               const __nv_bfloat16* __restrict__ Wh, const __nv_bfloat16* __restrict__ Wl,
               const float* __restrict__ bias, const float* __restrict__ res,
               float* __restrict__ out, int N, int K)
{
    extern __shared__ char smem[];
    const uint32_t sb = smem_u32(smem);
    const int tid  = threadIdx.x;
    const int wid  = tid >> 5;
    const int lane = tid & 31;
    const int m0 = blockIdx.y * BM, n0 = blockIdx.x * BN;
    const int warp_m0 = (wid & 3) * 64;   // 4 warps along m
    const int warp_n0 = (wid >> 2) * 64;  // 2 warps along n

    const int nch = K / BK;

    auto load_chunk = [&](int stage, int k0) {
        #pragma unroll
        for (int qq = 0; qq < 24; qq++) {
            const int it = tid + qq * GT;       // 0..6143
            uint32_t soff;
            const __nv_bfloat16* gp;
            if (it < 4096) {                    // A (256 rows x 64)
                const int hl  = it >> 11;
                const int idx = it & 2047;
                const int r   = idx >> 3;
                const int u   = idx & 7;
                gp = (hl ? Al : Ah) + (size_t)(m0 + r) * K + k0 + u * 8;
                soff = stage * STAGE_BYTES + hl * 32768 + r * 128 +
                       ((u ^ (r & 7)) * 16);
            } else {                            // B (128 rows x 64)
                const int it2 = it - 4096;
                const int hl  = it2 >> 10;
                const int idx = it2 & 1023;
                const int r   = idx >> 3;
                const int u   = idx & 7;
                gp = (hl ? Wl : Wh) + (size_t)(n0 + r) * K + k0 + u * 8;
                soff = stage * STAGE_BYTES + SOFF_B + hl * 16384 + r * 128 +
                       ((u ^ (r & 7)) * 16);
            }
            cp16(sb + soff, gp);
        }
    };

    float acc[4][8][4];
    #pragma unroll
    for (int i = 0; i < 4; i++)
        #pragma unroll
        for (int j = 0; j < 8; j++)
            #pragma unroll
            for (int e = 0; e < 4; e++) acc[i][j][e] = 0.f;

    load_chunk(0, 0);   cp_commit();

    const int g  = lane >> 3;
    const int tg = lane & 7;
    const int rowA_off = (g & 1) * 8 + tg;
    const int rowB_off = (g >> 1) * 8 + tg;

    for (int c = 0; c < nch; c++) {
        cp_wait0();
        __syncthreads();
        if (c + 1 < nch) load_chunk((c + 1) & 1, (c + 1) * BK);
        cp_commit();

        const uint32_t stA = sb + (c & 1) * STAGE_BYTES;
        const uint32_t stB = stA + SOFF_B;

        #pragma unroll
        for (int kk = 0; kk < 4; kk++) {
            uint32_t ah[4][4], al[4][4];
            const int unitA = kk * 2 + (g >> 1);
            #pragma unroll
            for (int tm = 0; tm < 4; tm++) {
                const int r = warp_m0 + tm * 16 + rowA_off;
                const uint32_t a = stA + r * 128 + ((unitA ^ (r & 7)) * 16);
                ldsm4(ah[tm][0], ah[tm][1], ah[tm][2], ah[tm][3], a);
                ldsm4(al[tm][0], al[tm][1], al[tm][2], al[tm][3], a + 32768);
            }
            const int unitB = kk * 2 + (g & 1);
            #pragma unroll
            for (int bn = 0; bn < 4; bn++) {
                const int r = warp_n0 + bn * 16 + rowB_off;
                const uint32_t a = stB + r * 128 + ((unitB ^ (r & 7)) * 16);
                uint32_t bh[4], bl[4];
                ldsm4(bh[0], bh[1], bh[2], bh[3], a);
                ldsm4(bl[0], bl[1], bl[2], bl[3], a + 16384);
                #pragma unroll
                for (int tm = 0; tm < 4; tm++) {
                    mma16816(acc[tm][2*bn],   ah[tm], bh[0], bh[1]);
                    mma16816(acc[tm][2*bn],   ah[tm], bl[0], bl[1]);
                    mma16816(acc[tm][2*bn],   al[tm], bh[0], bh[1]);
                    mma16816(acc[tm][2*bn+1], ah[tm], bh[2], bh[3]);
                    mma16816(acc[tm][2*bn+1], ah[tm], bl[2], bl[3]);
                    mma16816(acc[tm][2*bn+1], al[tm], bh[2], bh[3]);
                }
            }
        }
    }

    // ---- epilogue ----
    const int r_lo = lane >> 2;
    const int c_lo = (lane & 3) * 2;
    #pragma unroll
    for (int tm = 0; tm < 4; tm++) {
        #pragma unroll
        for (int tn = 0; tn < 8; tn++) {
            const int n = n0 + warp_n0 + tn * 8 + c_lo;
            #pragma unroll
            for (int h = 0; h < 2; h++) {
                const int m = m0 + warp_m0 + tm * 16 + r_lo + h * 8;
                float v0 = acc[tm][tn][h * 2 + 0] + bias[n];
                float v1 = acc[tm][tn][h * 2 + 1] + bias[n + 1];
                if (MODE == 0) {
                    const int head  = n / (3 * HD);
                    const int rem   = n % (3 * HD);
                    const int which = rem / HD;
                    const int d     = rem % HD;
                    const int bI    = m / SS;
                    const int sI    = m % SS;
                    __nv_bfloat16 h0, l0, h1, l1;
                    split_bf16(v0, h0, l0);
                    split_bf16(v1, h1, l1);
                    const size_t dst = (((size_t)bI * HH + head) * SS + sI) * HD + d;
                    __nv_bfloat16* ph = (which == 0) ? g_qh : (which == 1) ? g_kh : g_vh;
                    __nv_bfloat16* pl = (which == 0) ? g_ql : (which == 1) ? g_kl : g_vl;
                    *(uint32_t*)(ph + dst) = pack_bf16(h0, h1);
                    *(uint32_t*)(pl + dst) = pack_bf16(l0, l1);
                } else if (MODE == 1 || MODE == 3) {
                    const size_t o = (size_t)m * N + n;
                    const float2 rr = *(const float2*)(res + o);
                    float2 ov; ov.x = v0 + rr.x; ov.y = v1 + rr.y;
                    *(float2*)(out + o) = ov;
                } else { // MODE 2: gelu -> hi/lo bf16
                    const size_t o = (size_t)m * N + n;
                    __nv_bfloat16 hh, ll;
                    float gv0 = gelu_tanh(v0), gv1 = gelu_tanh(v1);
                    split_bf16(gv0, hh, ll); g_act_hi[o]   = hh; g_act_lo[o]   = ll;
                    split_bf16(gv1, hh, ll); g_act_hi[o+1] = hh; g_act_lo[o+1] = ll;
                }
            }
        }
    }
}

// ---------------- HMMA flash attention (causal) ------------------------------
// Block: 128 queries, 8 warps, kv tiles of 64, double-buffered, single-sync.
// LPT scheduling: qblk = gridDim.x-1-blockIdx.x so heaviest CTAs launch first.
#define AQ  128
#define AKV 64
#define SQ_H 0
#define SQ_L 16384
#define SST(s) (32768 + (s)*32768)
#define SV_OFF 16384
#define ATTN_SMEM 98304

__global__ __launch_bounds__(256, 1) void attn_mma(
    const __nv_bfloat16* __restrict__ Qh, const __nv_bfloat16* __restrict__ Ql,
    const __nv_bfloat16* __restrict__ Kh, const __nv_bfloat16* __restrict__ Kl,
    const __nv_bfloat16* __restrict__ Vh, const __nv_bfloat16* __restrict__ Vl,
    __nv_bfloat16* __restrict__ Oh, __nv_bfloat16* __restrict__ Ol)
{
    extern __shared__ char smem[];
    const uint32_t sb = smem_u32(smem);
    const int tid  = threadIdx.x;
    const int wid  = tid >> 5;
    const int lane = tid & 31;
    const int bh   = blockIdx.y;
    const int qblk = gridDim.x - 1 - blockIdx.x;   // heavy blocks first (LPT)
    const int q0   = qblk * AQ;
    const int g  = lane >> 3;
    const int tg = lane & 7;

    const __nv_bfloat16* Qhb = Qh + (size_t)bh * SS * HD;
    const __nv_bfloat16* Qlb = Ql + (size_t)bh * SS * HD;
    const __nv_bfloat16* Khb = Kh + (size_t)bh * SS * HD;
    const __nv_bfloat16* Klb = Kl + (size_t)bh * SS * HD;
    const __nv_bfloat16* Vhb = Vh + (size_t)bh * SS * HD;
    const __nv_bfloat16* Vlb = Vl + (size_t)bh * SS * HD;

    // ---- Q tile load (hi/lo, 128x64, swizzled) ----
    #pragma unroll
    for (int qq = 0; qq < 8; qq++) {
        const int it = tid + qq * 256;
        const int hl = it >> 10;
        const int r  = (it >> 3) & 127;
        const int u  = it & 7;
        const __nv_bfloat16* src = (hl ? Qlb : Qhb) + (size_t)(q0 + r) * HD + u * 8;
        cp16(sb + (hl ? SQ_L : SQ_H) + r * 128 + ((u ^ (r & 7)) * 16), src);
    }

    const int nkv = 2 * qblk + 2;

    auto load_kv = [&](int stage, int kv0) {
        #pragma unroll
        for (int qq = 0; qq < 8; qq++) {
            const int it  = tid + qq * 256;
            const int mat = it >> 9;
            const int r   = (it >> 3) & 63;
            const int u   = it & 7;
            const __nv_bfloat16* src;
            if (mat == 0)      src = Khb + (size_t)(kv0 + r) * HD + u * 8;
            else if (mat == 1) src = Klb + (size_t)(kv0 + r) * HD + u * 8;
            else if (mat == 2) src = Vhb + (size_t)(kv0 + r) * HD + u * 8;
            else               src = Vlb + (size_t)(kv0 + r) * HD + u * 8;
            cp16(sb + SST(stage) + mat * 8192 + r * 128 + ((u ^ (r & 7)) * 16), src);
        }
    };

    load_kv(0, 0);
    cp_commit();
    cp_wait0();
    __syncthreads();

    uint32_t qfh[4][4], qfl[4][4];
    const int rowA_off = (g & 1) * 8 + tg;
    {
        #pragma unroll
        for (int t = 0; t < 4; t++) {
            const int r  = wid * 16 + rowA_off;
            const int uA = t * 2 + (g >> 1);
            const uint32_t a = sb + SQ_H + r * 128 + ((uA ^ (r & 7)) * 16);
            ldsm4(qfh[t][0], qfh[t][1], qfh[t][2], qfh[t][3], a);
            ldsm4(qfl[t][0], qfl[t][1], qfl[t][2], qfl[t][3], a + 16384);
        }
    }

    float m_i[2] = {-1e30f, -1e30f};
    float l_i[2] = {0.f, 0.f};
    float acc_o[8][4];
    #pragma unroll
    for (int nt = 0; nt < 8; nt++)
        #pragma unroll
        for (int e = 0; e < 4; e++) acc_o[nt][e] = 0.f;

    const int rowB_off = (g >> 1) * 8 + tg;

    for (int j = 0; j < nkv; j++) {
        const int kv0 = j * AKV;
        if (j > 0) { cp_wait0(); __syncthreads(); }
        if (j + 1 < nkv) { load_kv((j + 1) & 1, (j + 1) * AKV); cp_commit(); }

        const uint32_t st = sb + SST(j & 1);

        float accs[8][4];
        #pragma unroll
        for (int nt = 0; nt < 8; nt++)
            #pragma unroll
            for (int e = 0; e < 4; e++) accs[nt][e] = 0.f;

        #pragma unroll
        for (int t = 0; t < 4; t++) {
            const int uB = t * 2 + (g & 1);
            #pragma unroll
            for (int bn = 0; bn < 4; bn++) {
                const int r = bn * 16 + rowB_off;
                const uint32_t a = st + r * 128 + ((uB ^ (r & 7)) * 16);
                uint32_t kbh[4], kbl[4];
                ldsm4(kbh[0], kbh[1], kbh[2], kbh[3], a);
                ldsm4(kbl[0], kbl[1], kbl[2], kbl[3], a + 8192);
                mma16816(accs[2*bn],   qfh[t], kbh[0], kbh[1]);
                mma16816(accs[2*bn],   qfh[t], kbl[0], kbl[1]);
                mma16816(accs[2*bn],   qfl[t], kbh[0], kbh[1]);
                mma16816(accs[2*bn+1], qfh[t], kbh[2], kbh[3]);
                mma16816(accs[2*bn+1], qfh[t], kbl[2], kbl[3]);
                mma16816(accs[2*bn+1], qfl[t], kbh[2], kbh[3]);
            }
        }
        #pragma unroll
        for (int nt = 0; nt < 8; nt++)
            #pragma unroll
            for (int e = 0; e < 4; e++) accs[nt][e] *= 0.125f;

        if (kv0 + AKV - 1 > q0 + wid * 16) {
            #pragma unroll
            for (int nt = 0; nt < 8; nt++)
                #pragma unroll
                for (int e = 0; e < 4; e++) {
                    const int row = q0 + wid * 16 + (lane >> 2) + ((e >> 1) ? 8 : 0);
                    const int col = kv0 + nt * 8 + 2 * (lane & 3) + (e & 1);
                    if (col > row) accs[nt][e] = -1e30f;
                }
        }

        #pragma unroll
        for (int h = 0; h < 2; h++) {
            float rm = -1e30f;
            #pragma unroll
            for (int nt = 0; nt < 8; nt++)
                rm = fmaxf(rm, fmaxf(accs[nt][2*h], accs[nt][2*h+1]));
            rm = fmaxf(rm, __shfl_xor_sync(0xffffffffu, rm, 1));
            rm = fmaxf(rm, __shfl_xor_sync(0xffffffffu, rm, 2));
            const float mnew = fmaxf(m_i[h], rm);
            const float corr = __expf(m_i[h] - mnew);
            m_i[h] = mnew;
            float rs = 0.f;
            #pragma unroll
            for (int nt = 0; nt < 8; nt++) {
                accs[nt][2*h]   = __expf(accs[nt][2*h]   - mnew);
                accs[nt][2*h+1] = __expf(accs[nt][2*h+1] - mnew);
                rs += accs[nt][2*h] + accs[nt][2*h+1];
            }
            rs += __shfl_xor_sync(0xffffffffu, rs, 1);
            rs += __shfl_xor_sync(0xffffffffu, rs, 2);
            l_i[h] = l_i[h] * corr + rs;
            #pragma unroll
            for (int nt = 0; nt < 8; nt++) {
                acc_o[nt][2*h]   *= corr;
                acc_o[nt][2*h+1] *= corr;
            }
        }

        uint32_t pfh[4][4], pfl[4][4];
        #pragma unroll
        for (int t = 0; t < 4; t++) {
            #pragma unroll
            for (int half = 0; half < 2; half++) {
                const int nt = 2 * t + half;
                __nv_bfloat16 h0, l0, h1, l1, h2, l2, h3, l3;
                split_bf16(accs[nt][0], h0, l0);
                split_bf16(accs[nt][1], h1, l1);
                split_bf16(accs[nt][2], h2, l2);
                split_bf16(accs[nt][3], h3, l3);
                pfh[t][half*2+0] = pack_bf16(h0, h1);
                pfh[t][half*2+1] = pack_bf16(h2, h3);
                pfl[t][half*2+0] = pack_bf16(l0, l1);
                pfl[t][half*2+1] = pack_bf16(l2, l3);
            }
        }

        #pragma unroll
        for (int t = 0; t < 4; t++) {
            #pragma unroll
            for (int bn = 0; bn < 4; bn++) {
                const int r = t * 16 + rowA_off;
                const int u = bn * 2 + (g >> 1);
                const uint32_t a = st + SV_OFF + r * 128 + ((u ^ (r & 7)) * 16);
                uint32_t vbh[4], vbl[4];
                ldsm4t(vbh[0], vbh[1], vbh[2], vbh[3], a);
                ldsm4t(vbl[0], vbl[1], vbl[2], vbl[3], a + 8192);
                mma16816(acc_o[2*bn],   pfh[t], vbh[0], vbh[1]);
                mma16816(acc_o[2*bn],   pfh[t], vbl[0], vbl[1]);
                mma16816(acc_o[2*bn],   pfl[t], vbh[0], vbh[1]);
                mma16816(acc_o[2*bn+1], pfh[t], vbh[2], vbh[3]);
                mma16816(acc_o[2*bn+1], pfh[t], vbl[2], vbl[3]);
                mma16816(acc_o[2*bn+1], pfl[t], vbh[2], vbh[3]);
            }
        }
    }

    // ---- epilogue: O / l_i -> at hi/lo [B,S,E] ----
    const int bI = bh / HH;
    const int hI = bh % HH;
    #pragma unroll
    for (int h = 0; h < 2; h++) {
        const float inv = 1.0f / l_i[h];
        const int sI = q0 + wid * 16 + (lane >> 2) + h * 8;
        const size_t base = ((size_t)bI * SS + sI) * EE + hI * HD;
        #pragma unroll
        for (int nt = 0; nt < 8; nt++) {
            const int d = nt * 8 + 2 * (lane & 3);
            __nv_bfloat16 h0, l0, h1, l1;
            split_bf16(acc_o[nt][2*h]   * inv, h0, l0);
            split_bf16(acc_o[nt][2*h+1] * inv, h1, l1);
            *(uint32_t*)(Oh + base + d) = pack_bf16(h0, h1);
            *(uint32_t*)(Ol + base + d) = pack_bf16(l0, l1);
        }
    }
}

// ---------------- launch ----------------------------------------------------
extern "C" void kernel_launch(void* const* d_in, const int* in_sizes, int n_in,
                              void* d_out, int out_size)
{
    const float* x     = (const float*)d_in[0];
    const float* ln1_g = (const float*)d_in[1];
    const float* ln1_b = (const float*)d_in[2];
    const float* ln2_g = (const float*)d_in[3];
    const float* ln2_b = (const float*)d_in[4];
    const float* w_qkv = (const float*)d_in[5];
    const float* b_qkv = (const float*)d_in[6];
    const float* w_ao  = (const float*)d_in[7];
    const float* b_ao  = (const float*)d_in[8];
    const float* w_fc  = (const float*)d_in[9];
    const float* b_fc  = (const float*)d_in[10];
    const float* w_po  = (const float*)d_in[11];
    const float* b_po  = (const float*)d_in[12];
    float* out = (float*)d_out;

    float *x1;
    __nv_bfloat16 *qh, *ql, *kh, *kl, *vh, *vl;
    __nv_bfloat16 *lnh, *lnl, *ath, *atl, *acth, *actl;
    __nv_bfloat16 *wqh, *wql, *waoh, *waol, *wfh, *wfl, *wph, *wpl;
    cudaGetSymbolAddress((void**)&x1,  g_x1);
    cudaGetSymbolAddress((void**)&qh,  g_qh);
    cudaGetSymbolAddress((void**)&ql,  g_ql);
    cudaGetSymbolAddress((void**)&kh,  g_kh);
    cudaGetSymbolAddress((void**)&kl,  g_kl);
    cudaGetSymbolAddress((void**)&vh,  g_vh);
    cudaGetSymbolAddress((void**)&vl,  g_vl);
    cudaGetSymbolAddress((void**)&lnh, g_ln_hi);
    cudaGetSymbolAddress((void**)&lnl, g_ln_lo);
    cudaGetSymbolAddress((void**)&ath, g_at_hi);
    cudaGetSymbolAddress((void**)&atl, g_at_lo);
    cudaGetSymbolAddress((void**)&acth, g_act_hi);
    cudaGetSymbolAddress((void**)&actl, g_act_lo);
    cudaGetSymbolAddress((void**)&wqh, g_wqkv_hi);
    cudaGetSymbolAddress((void**)&wql, g_wqkv_lo);
    cudaGetSymbolAddress((void**)&waoh, g_wao_hi);
    cudaGetSymbolAddress((void**)&waol, g_wao_lo);
    cudaGetSymbolAddress((void**)&wfh, g_wfc_hi);
    cudaGetSymbolAddress((void**)&wfl, g_wfc_lo);
    cudaGetSymbolAddress((void**)&wph, g_wpo_hi);
    cudaGetSymbolAddress((void**)&wpl, g_wpo_lo);

    cudaFuncSetAttribute(attn_mma,     cudaFuncAttributeMaxDynamicSharedMemorySize, ATTN_SMEM);
    cudaFuncSetAttribute(hmma_gemm<0>, cudaFuncAttributeMaxDynamicSharedMemorySize, GEMM_SMEM);
    cudaFuncSetAttribute(hmma_gemm<1>, cudaFuncAttributeMaxDynamicSharedMemorySize, GEMM_SMEM);
    cudaFuncSetAttribute(hmma_gemm<2>, cudaFuncAttributeMaxDynamicSharedMemorySize, GEMM_SMEM);
    cudaFuncSetAttribute(hmma_gemm<3>, cudaFuncAttributeMaxDynamicSharedMemorySize, GEMM_SMEM);

    // fused weight conversion + LN1 (single launch)
    cvt_ln1_kernel<<<CVT_BLOCKS + MM, 256>>>(w_qkv, w_ao, w_fc, w_po, x, ln1_g, ln1_b);

    // 2. QKV GEMM (M=4096, N=3072, K=1024), emit Q/K/V hi-lo [B,H,S,HD]
    hmma_gemm<0><<<dim3(3*EE/BN, MM/BM), GT, GEMM_SMEM>>>(
        lnh, lnl, wqh, wql, b_qkv, nullptr, nullptr, 3*EE, EE);
    // 3. HMMA causal flash attention (LPT order) -> at hi/lo
    attn_mma<<<dim3(SS/AQ, BB*HH), 256, ATTN_SMEM>>>(qh, ql, kh, kl, vh, vl, ath, atl);
    // 4. AO GEMM + residual -> x1 (fp32)
    hmma_gemm<1><<<dim3(EE/BN, MM/BM), GT, GEMM_SMEM>>>(
        ath, atl, waoh, waol, b_ao, x, x1, EE, EE);
    // 5. LN2 -> hi/lo
    ln_kernel<<<MM, 256>>>(x1, ln2_g, ln2_b, lnh, lnl);
    // 6. FC GEMM + gelu -> act hi/lo
    hmma_gemm<2><<<dim3(DFF/BN, MM/BM), GT, GEMM_SMEM>>>(
        lnh, lnl, wfh, wfl, b_fc, nullptr, nullptr, DFF, EE);
    // 7. PO GEMM + residual -> out
    hmma_gemm<3><<<dim3(EE/BN, MM/BM), GT, GEMM_SMEM>>>(
        acth, actl, wph, wpl, b_po, x1, out, EE, DFF);
}

// round 16
// speedup vs baseline: 1.0639x; 1.0340x over previous
#include <cuda_runtime.h>
#include <cuda_bf16.h>
#include <math.h>
#include <stdint.h>

// Problem constants
#define BB   2
#define SS   2048
#define EE   1024
#define HH   16
#define HD   64
#define DFF  4096
#define MM   (BB*SS)   // 4096 tokens

// ---------------- scratch (device globals; no allocations allowed) ----------
__device__ __align__(128) float g_x1[(size_t)MM*EE];     // residual after attn

__device__ __align__(128) __nv_bfloat16 g_qh [(size_t)MM*EE],  g_ql [(size_t)MM*EE];  // [B,H,S,HD]
__device__ __align__(128) __nv_bfloat16 g_kh [(size_t)MM*EE],  g_kl [(size_t)MM*EE];  // [B,H,S,HD]
__device__ __align__(128) __nv_bfloat16 g_vh [(size_t)MM*EE],  g_vl [(size_t)MM*EE];  // [B,H,S,HD]

__device__ __align__(128) __nv_bfloat16 g_ln_hi [(size_t)MM*EE],  g_ln_lo [(size_t)MM*EE];
__device__ __align__(128) __nv_bfloat16 g_at_hi [(size_t)MM*EE],  g_at_lo [(size_t)MM*EE];
__device__ __align__(128) __nv_bfloat16 g_act_hi[(size_t)MM*DFF], g_act_lo[(size_t)MM*DFF];

__device__ __align__(128) __nv_bfloat16 g_wqkv_hi[(size_t)3*EE*EE], g_wqkv_lo[(size_t)3*EE*EE];
__device__ __align__(128) __nv_bfloat16 g_wao_hi [(size_t)EE*EE],   g_wao_lo [(size_t)EE*EE];
__device__ __align__(128) __nv_bfloat16 g_wfc_hi [(size_t)DFF*EE],  g_wfc_lo [(size_t)DFF*EE];
__device__ __align__(128) __nv_bfloat16 g_wpo_hi [(size_t)EE*DFF],  g_wpo_lo [(size_t)EE*DFF];

// ---------------- helpers ----------------------------------------------------
__device__ __forceinline__ uint32_t smem_u32(const void* p) {
    uint32_t a;
    asm("{ .reg .u64 t; cvta.to.shared.u64 t, %1; cvt.u32.u64 %0, t; }"
        : "=r"(a) : "l"(p));
    return a;
}
__device__ __forceinline__ void cp16(uint32_t saddr, const void* gptr) {
    asm volatile("cp.async.cg.shared.global [%0], [%1], 16;"
                 :: "r"(saddr), "l"(gptr));
}
__device__ __forceinline__ void cp_commit() {
    asm volatile("cp.async.commit_group;" ::: "memory");
}
__device__ __forceinline__ void cp_wait0() {
    asm volatile("cp.async.wait_group 0;" ::: "memory");
}
__device__ __forceinline__ void ldsm4(uint32_t& r0, uint32_t& r1, uint32_t& r2,
                                      uint32_t& r3, uint32_t addr) {
    asm volatile("ldmatrix.sync.aligned.m8n8.x4.shared.b16 {%0,%1,%2,%3}, [%4];"
                 : "=r"(r0), "=r"(r1), "=r"(r2), "=r"(r3) : "r"(addr));
}
__device__ __forceinline__ void ldsm4t(uint32_t& r0, uint32_t& r1, uint32_t& r2,
                                       uint32_t& r3, uint32_t addr) {
    asm volatile("ldmatrix.sync.aligned.m8n8.x4.trans.shared.b16 {%0,%1,%2,%3}, [%4];"
                 : "=r"(r0), "=r"(r1), "=r"(r2), "=r"(r3) : "r"(addr));
}
__device__ __forceinline__ void mma16816(float* c, const uint32_t* a,
                                         uint32_t b0, uint32_t b1) {
    asm volatile(
        "mma.sync.aligned.m16n8k16.row.col.f32.bf16.bf16.f32 "
        "{%0,%1,%2,%3}, {%4,%5,%6,%7}, {%8,%9}, {%0,%1,%2,%3};"
        : "+f"(c[0]), "+f"(c[1]), "+f"(c[2]), "+f"(c[3])
        : "r"(a[0]), "r"(a[1]), "r"(a[2]), "r"(a[3]), "r"(b0), "r"(b1));
}

__device__ __forceinline__ float gelu_tanh(float x) {
    // tanh(u) = 1 - 2/(1+e^{2u});  gelu = 0.5x(1+tanh(u))
    const float c = 0.7978845608028654f;
    const float u = c * (x + 0.044715f * x * x * x);
    const float t = 1.0f - 2.0f / (1.0f + __expf(2.0f * u));
    return 0.5f * x * (1.0f + t);
}
__device__ __forceinline__ void split_bf16(float v, __nv_bfloat16& h, __nv_bfloat16& l) {
    h = __float2bfloat16(v);
    l = __float2bfloat16(v - __bfloat162float(h));
}
__device__ __forceinline__ uint32_t pack_bf16(__nv_bfloat16 a, __nv_bfloat16 b) {
    uint16_t ua = *reinterpret_cast<uint16_t*>(&a);
    uint16_t ub = *reinterpret_cast<uint16_t*>(&b);
    return (uint32_t)ua | ((uint32_t)ub << 16);
}

// ---------------- LayerNorm row body ------------------------------------------
__device__ __forceinline__ void ln_row(
    const float* __restrict__ x, const float* __restrict__ g,
    const float* __restrict__ b, __nv_bfloat16* __restrict__ oh,
    __nv_bfloat16* __restrict__ ol, int row)
{
    const int t = threadIdx.x;
    const float4 v = ((const float4*)(x + (size_t)row * EE))[t];

    float s  = v.x + v.y + v.z + v.w;
    float ss = v.x*v.x + v.y*v.y + v.z*v.z + v.w*v.w;

    __shared__ float ws[8], wss[8];
    __shared__ float s_mu, s_rstd;
    const unsigned lane = t & 31u, w = t >> 5;
    #pragma unroll
    for (int off = 16; off; off >>= 1) {
        s  += __shfl_down_sync(0xffffffffu, s,  off);
        ss += __shfl_down_sync(0xffffffffu, ss, off);
    }
    if (lane == 0) { ws[w] = s; wss[w] = ss; }
    __syncthreads();
    if (t == 0) {
        float ts = 0.f, tss = 0.f;
        #pragma unroll
        for (int i = 0; i < 8; i++) { ts += ws[i]; tss += wss[i]; }
        const float mu  = ts * (1.0f / EE);
        const float var = tss * (1.0f / EE) - mu * mu;
        s_mu = mu; s_rstd = rsqrtf(var + 1e-5f);
    }
    __syncthreads();
    const float mu = s_mu, rstd = s_rstd;
    const float4 gg = ((const float4*)g)[t];
    const float4 bb = ((const float4*)b)[t];
    float o0 = (v.x - mu)*rstd*gg.x + bb.x;
    float o1 = (v.y - mu)*rstd*gg.y + bb.y;
    float o2 = (v.z - mu)*rstd*gg.z + bb.z;
    float o3 = (v.w - mu)*rstd*gg.w + bb.w;
    const size_t base = (size_t)row * EE + t * 4;
    __nv_bfloat16 h, l;
    split_bf16(o0, h, l); oh[base+0] = h; ol[base+0] = l;
    split_bf16(o1, h, l); oh[base+1] = h; ol[base+1] = l;
    split_bf16(o2, h, l); oh[base+2] = h; ol[base+2] = l;
    split_bf16(o3, h, l); oh[base+3] = h; ol[base+3] = l;
}

__global__ __launch_bounds__(256) void ln_kernel(
    const float* __restrict__ x, const float* __restrict__ g,
    const float* __restrict__ b, __nv_bfloat16* __restrict__ oh,
    __nv_bfloat16* __restrict__ ol)
{
    ln_row(x, g, b, oh, ol, blockIdx.x);
}

// ---------------- fused weight cvt + LN1 (single launch) ---------------------
#define N4_QKV  (3*EE*EE/4)
#define N4_AO   (EE*EE/4)
#define N4_FC   (DFF*EE/4)
#define N4_PO   (EE*DFF/4)
#define N4_ALL  (N4_QKV + N4_AO + N4_FC + N4_PO)
#define CVT_BLOCKS ((N4_ALL + 255) / 256)

__global__ __launch_bounds__(256) void cvt_ln1_kernel(
    const float* __restrict__ s_qkv, const float* __restrict__ s_ao,
    const float* __restrict__ s_fc,  const float* __restrict__ s_po,
    const float* __restrict__ x, const float* __restrict__ ln1_g,
    const float* __restrict__ ln1_b)
{
    if (blockIdx.x >= CVT_BLOCKS) {
        ln_row(x, ln1_g, ln1_b, g_ln_hi, g_ln_lo, blockIdx.x - CVT_BLOCKS);
        return;
    }
    int i = blockIdx.x * 256 + threadIdx.x;
    if (i >= N4_ALL) return;
    const float* src;
    __nv_bfloat16 *hi, *lo;
    if (i < N4_QKV)                      { src = s_qkv; hi = g_wqkv_hi; lo = g_wqkv_lo; }
    else if (i < N4_QKV + N4_AO)         { i -= N4_QKV; src = s_ao; hi = g_wao_hi; lo = g_wao_lo; }
    else if (i < N4_QKV + N4_AO + N4_FC) { i -= N4_QKV + N4_AO; src = s_fc; hi = g_wfc_hi; lo = g_wfc_lo; }
    else                                 { i -= N4_QKV + N4_AO + N4_FC; src = s_po; hi = g_wpo_hi; lo = g_wpo_lo; }
    const float4 v = ((const float4*)src)[i];
    __nv_bfloat16 h, l;
    const size_t base = (size_t)i * 4;
    split_bf16(v.x, h, l); hi[base+0] = h; lo[base+0] = l;
    split_bf16(v.y, h, l); hi[base+1] = h; lo[base+1] = l;
    split_bf16(v.z, h, l); hi[base+2] = h; lo[base+2] = l;
    split_bf16(v.w, h, l); hi[base+3] = h; lo[base+3] = l;
}

// ---------------- HMMA bf16x3 GEMM, 256x128 tiles (QKV / AO / PO) ------------
#define BM 256
#define BN 128
#define BK 64
#define GT 256
#define STAGE_BYTES 98304
#define SOFF_B 65536
#define GEMM_SMEM (2*STAGE_BYTES) // 196608

template<int MODE>
__global__ __launch_bounds__(GT, 1)
void hmma_gemm(const __nv_bfloat16* __restrict__ Ah, const __nv_bfloat16* __restrict__ Al,
               const __nv_bfloat16* __restrict__ Wh, const __nv_bfloat16* __restrict__ Wl,
               const float* __restrict__ bias, const float* __restrict__ res,
               float* __restrict__ out, int N, int K)
{
    extern __shared__ char smem[];
    const uint32_t sb = smem_u32(smem);
    const int tid  = threadIdx.x;
    const int wid  = tid >> 5;
    const int lane = tid & 31;
    const int m0 = blockIdx.y * BM, n0 = blockIdx.x * BN;
    const int warp_m0 = (wid & 3) * 64;
    const int warp_n0 = (wid >> 2) * 64;

    const int nch = K / BK;

    auto load_chunk = [&](int stage, int k0) {
        #pragma unroll
        for (int qq = 0; qq < 24; qq++) {
            const int it = tid + qq * GT;
            uint32_t soff;
            const __nv_bfloat16* gp;
            if (it < 4096) {                    // A (256 rows x 64)
                const int hl  = it >> 11;
                const int idx = it & 2047;
                const int r   = idx >> 3;
                const int u   = idx & 7;
                gp = (hl ? Al : Ah) + (size_t)(m0 + r) * K + k0 + u * 8;
                soff = stage * STAGE_BYTES + hl * 32768 + r * 128 +
                       ((u ^ (r & 7)) * 16);
            } else {                            // B (128 rows x 64)
                const int it2 = it - 4096;
                const int hl  = it2 >> 10;
                const int idx = it2 & 1023;
                const int r   = idx >> 3;
                const int u   = idx & 7;
                gp = (hl ? Wl : Wh) + (size_t)(n0 + r) * K + k0 + u * 8;
                soff = stage * STAGE_BYTES + SOFF_B + hl * 16384 + r * 128 +
                       ((u ^ (r & 7)) * 16);
            }
            cp16(sb + soff, gp);
        }
    };

    float acc[4][8][4];
    #pragma unroll
    for (int i = 0; i < 4; i++)
        #pragma unroll
        for (int j = 0; j < 8; j++)
            #pragma unroll
            for (int e = 0; e < 4; e++) acc[i][j][e] = 0.f;

    load_chunk(0, 0);   cp_commit();

    const int g  = lane >> 3;
    const int tg = lane & 7;
    const int rowA_off = (g & 1) * 8 + tg;
    const int rowB_off = (g >> 1) * 8 + tg;

    for (int c = 0; c < nch; c++) {
        cp_wait0();
        __syncthreads();
        if (c + 1 < nch) load_chunk((c + 1) & 1, (c + 1) * BK);
        cp_commit();

        const uint32_t stA = sb + (c & 1) * STAGE_BYTES;
        const uint32_t stB = stA + SOFF_B;

        #pragma unroll
        for (int kk = 0; kk < 4; kk++) {
            uint32_t ah[4][4], al[4][4];
            const int unitA = kk * 2 + (g >> 1);
            #pragma unroll
            for (int tm = 0; tm < 4; tm++) {
                const int r = warp_m0 + tm * 16 + rowA_off;
                const uint32_t a = stA + r * 128 + ((unitA ^ (r & 7)) * 16);
                ldsm4(ah[tm][0], ah[tm][1], ah[tm][2], ah[tm][3], a);
                ldsm4(al[tm][0], al[tm][1], al[tm][2], al[tm][3], a + 32768);
            }
            const int unitB = kk * 2 + (g & 1);
            #pragma unroll
            for (int bn = 0; bn < 4; bn++) {
                const int r = warp_n0 + bn * 16 + rowB_off;
                const uint32_t a = stB + r * 128 + ((unitB ^ (r & 7)) * 16);
                uint32_t bh[4], bl[4];
                ldsm4(bh[0], bh[1], bh[2], bh[3], a);
                ldsm4(bl[0], bl[1], bl[2], bl[3], a + 16384);
                #pragma unroll
                for (int tm = 0; tm < 4; tm++) {
                    mma16816(acc[tm][2*bn],   ah[tm], bh[0], bh[1]);
                    mma16816(acc[tm][2*bn],   ah[tm], bl[0], bl[1]);
                    mma16816(acc[tm][2*bn],   al[tm], bh[0], bh[1]);
                    mma16816(acc[tm][2*bn+1], ah[tm], bh[2], bh[3]);
                    mma16816(acc[tm][2*bn+1], ah[tm], bl[2], bl[3]);
                    mma16816(acc[tm][2*bn+1], al[tm], bh[2], bh[3]);
                }
            }
        }
    }

    // ---- epilogue ----
    const int r_lo = lane >> 2;
    const int c_lo = (lane & 3) * 2;
    #pragma unroll
    for (int tm = 0; tm < 4; tm++) {
        #pragma unroll
        for (int tn = 0; tn < 8; tn++) {
            const int n = n0 + warp_n0 + tn * 8 + c_lo;
            #pragma unroll
            for (int h = 0; h < 2; h++) {
                const int m = m0 + warp_m0 + tm * 16 + r_lo + h * 8;
                float v0 = acc[tm][tn][h * 2 + 0] + bias[n];
                float v1 = acc[tm][tn][h * 2 + 1] + bias[n + 1];
                if (MODE == 0) {
                    const int head  = n / (3 * HD);
                    const int rem   = n % (3 * HD);
                    const int which = rem / HD;
                    const int d     = rem % HD;
                    const int bI    = m / SS;
                    const int sI    = m % SS;
                    __nv_bfloat16 h0, l0, h1, l1;
                    split_bf16(v0, h0, l0);
                    split_bf16(v1, h1, l1);
                    const size_t dst = (((size_t)bI * HH + head) * SS + sI) * HD + d;
                    __nv_bfloat16* ph = (which == 0) ? g_qh : (which == 1) ? g_kh : g_vh;
                    __nv_bfloat16* pl = (which == 0) ? g_ql : (which == 1) ? g_kl : g_vl;
                    *(uint32_t*)(ph + dst) = pack_bf16(h0, h1);
                    *(uint32_t*)(pl + dst) = pack_bf16(l0, l1);
                } else { // MODE 1 / 3: +bias +residual -> fp32
                    const size_t o = (size_t)m * N + n;
                    const float2 rr = *(const float2*)(res + o);
                    float2 ov; ov.x = v0 + rr.x; ov.y = v1 + rr.y;
                    *(float2*)(out + o) = ov;
                }
            }
        }
    }
}

// ---------------- HMMA bf16x3 GEMM, 128x128 tiles (FC, gelu epilogue) --------
// 1024 CTAs for FC -> 6.92 waves, quantization waste 1.2% (vs 15.6%).
#define BM2 128
#define BN2 128
#define STAGE2_BYTES 65536
#define S2OFF_B 32768
#define GEMM2_SMEM (2*STAGE2_BYTES) // 131072

__global__ __launch_bounds__(GT, 1)
void hmma_gemm_fc(const __nv_bfloat16* __restrict__ Ah, const __nv_bfloat16* __restrict__ Al,
                  const __nv_bfloat16* __restrict__ Wh, const __nv_bfloat16* __restrict__ Wl,
                  const float* __restrict__ bias, int N, int K)
{
    extern __shared__ char smem[];
    const uint32_t sb = smem_u32(smem);
    const int tid  = threadIdx.x;
    const int wid  = tid >> 5;
    const int lane = tid & 31;
    const int m0 = blockIdx.y * BM2, n0 = blockIdx.x * BN2;
    const int warp_m0 = (wid & 1) * 64;   // 2 warps along m
    const int warp_n0 = (wid >> 1) * 32;  // 4 warps along n

    const int nch = K / BK;

    // per stage: 4096 x 16B units: A hi/lo (1024 each), B hi/lo (1024 each)
    auto load_chunk = [&](int stage, int k0) {
        #pragma unroll
        for (int qq = 0; qq < 16; qq++) {
            const int it = tid + qq * GT;       // 0..4095
            const int half = it >> 11;          // 0 = A, 1 = B
            const int hl   = (it >> 10) & 1;
            const int idx  = it & 1023;
            const int r    = idx >> 3;
            const int u    = idx & 7;
            const __nv_bfloat16* gp = half
                ? ((hl ? Wl : Wh) + (size_t)(n0 + r) * K + k0 + u * 8)
                : ((hl ? Al : Ah) + (size_t)(m0 + r) * K + k0 + u * 8);
            const uint32_t soff = stage * STAGE2_BYTES + half * S2OFF_B +
                                  hl * 16384 + r * 128 + ((u ^ (r & 7)) * 16);
            cp16(sb + soff, gp);
        }
    };

    float acc[4][4][4];
    #pragma unroll
    for (int i = 0; i < 4; i++)
        #pragma unroll
        for (int j = 0; j < 4; j++)
            #pragma unroll
            for (int e = 0; e < 4; e++) acc[i][j][e] = 0.f;

    load_chunk(0, 0);   cp_commit();

    const int g  = lane >> 3;
    const int tg = lane & 7;
    const int rowA_off = (g & 1) * 8 + tg;
    const int rowB_off = (g >> 1) * 8 + tg;

    for (int c = 0; c < nch; c++) {
        cp_wait0();
        __syncthreads();
        if (c + 1 < nch) load_chunk((c + 1) & 1, (c + 1) * BK);
        cp_commit();

        const uint32_t stA = sb + (c & 1) * STAGE2_BYTES;
        const uint32_t stB = stA + S2OFF_B;

        #pragma unroll
        for (int kk = 0; kk < 4; kk++) {
            uint32_t ah[4][4], al[4][4];
            const int unitA = kk * 2 + (g >> 1);
            #pragma unroll
            for (int tm = 0; tm < 4; tm++) {
                const int r = warp_m0 + tm * 16 + rowA_off;
                const uint32_t a = stA + r * 128 + ((unitA ^ (r & 7)) * 16);
                ldsm4(ah[tm][0], ah[tm][1], ah[tm][2], ah[tm][3], a);
                ldsm4(al[tm][0], al[tm][1], al[tm][2], al[tm][3], a + 16384);
            }
            const int unitB = kk * 2 + (g & 1);
            #pragma unroll
            for (int bn = 0; bn < 2; bn++) {
                const int r = warp_n0 + bn * 16 + rowB_off;
                const uint32_t a = stB + r * 128 + ((unitB ^ (r & 7)) * 16);
                uint32_t bh[4], bl[4];
                ldsm4(bh[0], bh[1], bh[2], bh[3], a);
                ldsm4(bl[0], bl[1], bl[2], bl[3], a + 16384);
                #pragma unroll
                for (int tm = 0; tm < 4; tm++) {
                    mma16816(acc[tm][2*bn],   ah[tm], bh[0], bh[1]);
                    mma16816(acc[tm][2*bn],   ah[tm], bl[0], bl[1]);
                    mma16816(acc[tm][2*bn],   al[tm], bh[0], bh[1]);
                    mma16816(acc[tm][2*bn+1], ah[tm], bh[2], bh[3]);
                    mma16816(acc[tm][2*bn+1], ah[tm], bl[2], bl[3]);
                    mma16816(acc[tm][2*bn+1], al[tm], bh[2], bh[3]);
                }
            }
        }
    }

    // ---- epilogue: gelu -> hi/lo bf16 ----
    const int r_lo = lane >> 2;
    const int c_lo = (lane & 3) * 2;
    #pragma unroll
    for (int tm = 0; tm < 4; tm++) {
        #pragma unroll
        for (int tn = 0; tn < 4; tn++) {
            const int n = n0 + warp_n0 + tn * 8 + c_lo;
            #pragma unroll
            for (int h = 0; h < 2; h++) {
                const int m = m0 + warp_m0 + tm * 16 + r_lo + h * 8;
                float v0 = acc[tm][tn][h * 2 + 0] + bias[n];
                float v1 = acc[tm][tn][h * 2 + 1] + bias[n + 1];
                const size_t o = (size_t)m * N + n;
                __nv_bfloat16 hh, ll;
                split_bf16(gelu_tanh(v0), hh, ll); g_act_hi[o]   = hh; g_act_lo[o]   = ll;
                split_bf16(gelu_tanh(v1), hh, ll); g_act_hi[o+1] = hh; g_act_lo[o+1] = ll;
            }
        }
    }
}

// ---------------- HMMA flash attention (causal, LPT) --------------------------
#define AQ  128
#define AKV 64
#define SQ_H 0
#define SQ_L 16384
#define SST(s) (32768 + (s)*32768)
#define SV_OFF 16384
#define ATTN_SMEM 98304

__global__ __launch_bounds__(256, 1) void attn_mma(
    const __nv_bfloat16* __restrict__ Qh, const __nv_bfloat16* __restrict__ Ql,
    const __nv_bfloat16* __restrict__ Kh, const __nv_bfloat16* __restrict__ Kl,
    const __nv_bfloat16* __restrict__ Vh, const __nv_bfloat16* __restrict__ Vl,
    __nv_bfloat16* __restrict__ Oh, __nv_bfloat16* __restrict__ Ol)
{
    extern __shared__ char smem[];
    const uint32_t sb = smem_u32(smem);
    const int tid  = threadIdx.x;
    const int wid  = tid >> 5;
    const int lane = tid & 31;
    const int bh   = blockIdx.y;
    const int qblk = gridDim.x - 1 - blockIdx.x;   // heavy blocks first (LPT)
    const int q0   = qblk * AQ;
    const int g  = lane >> 3;
    const int tg = lane & 7;

    const __nv_bfloat16* Qhb = Qh + (size_t)bh * SS * HD;
    const __nv_bfloat16* Qlb = Ql + (size_t)bh * SS * HD;
    const __nv_bfloat16* Khb = Kh + (size_t)bh * SS * HD;
    const __nv_bfloat16* Klb = Kl + (size_t)bh * SS * HD;
    const __nv_bfloat16* Vhb = Vh + (size_t)bh * SS * HD;
    const __nv_bfloat16* Vlb = Vl + (size_t)bh * SS * HD;

    #pragma unroll
    for (int qq = 0; qq < 8; qq++) {
        const int it = tid + qq * 256;
        const int hl = it >> 10;
        const int r  = (it >> 3) & 127;
        const int u  = it & 7;
        const __nv_bfloat16* src = (hl ? Qlb : Qhb) + (size_t)(q0 + r) * HD + u * 8;
        cp16(sb + (hl ? SQ_L : SQ_H) + r * 128 + ((u ^ (r & 7)) * 16), src);
    }

    const int nkv = 2 * qblk + 2;

    auto load_kv = [&](int stage, int kv0) {
        #pragma unroll
        for (int qq = 0; qq < 8; qq++) {
            const int it  = tid + qq * 256;
            const int mat = it >> 9;
            const int r   = (it >> 3) & 63;
            const int u   = it & 7;
            const __nv_bfloat16* src;
            if (mat == 0)      src = Khb + (size_t)(kv0 + r) * HD + u * 8;
            else if (mat == 1) src = Klb + (size_t)(kv0 + r) * HD + u * 8;
            else if (mat == 2) src = Vhb + (size_t)(kv0 + r) * HD + u * 8;
            else               src = Vlb + (size_t)(kv0 + r) * HD + u * 8;
            cp16(sb + SST(stage) + mat * 8192 + r * 128 + ((u ^ (r & 7)) * 16), src);
        }
    };

    load_kv(0, 0);
    cp_commit();
    cp_wait0();
    __syncthreads();

    uint32_t qfh[4][4], qfl[4][4];
    const int rowA_off = (g & 1) * 8 + tg;
    {
        #pragma unroll
        for (int t = 0; t < 4; t++) {
            const int r  = wid * 16 + rowA_off;
            const int uA = t * 2 + (g >> 1);
            const uint32_t a = sb + SQ_H + r * 128 + ((uA ^ (r & 7)) * 16);
            ldsm4(qfh[t][0], qfh[t][1], qfh[t][2], qfh[t][3], a);
            ldsm4(qfl[t][0], qfl[t][1], qfl[t][2], qfl[t][3], a + 16384);
        }
    }

    float m_i[2] = {-1e30f, -1e30f};
    float l_i[2] = {0.f, 0.f};
    float acc_o[8][4];
    #pragma unroll
    for (int nt = 0; nt < 8; nt++)
        #pragma unroll
        for (int e = 0; e < 4; e++) acc_o[nt][e] = 0.f;

    const int rowB_off = (g >> 1) * 8 + tg;

    for (int j = 0; j < nkv; j++) {
        const int kv0 = j * AKV;
        if (j > 0) { cp_wait0(); __syncthreads(); }
        if (j + 1 < nkv) { load_kv((j + 1) & 1, (j + 1) * AKV); cp_commit(); }

        const uint32_t st = sb + SST(j & 1);

        float accs[8][4];
        #pragma unroll
        for (int nt = 0; nt < 8; nt++)
            #pragma unroll
            for (int e = 0; e < 4; e++) accs[nt][e] = 0.f;

        #pragma unroll
        for (int t = 0; t < 4; t++) {
            const int uB = t * 2 + (g & 1);
            #pragma unroll
            for (int bn = 0; bn < 4; bn++) {
                const int r = bn * 16 + rowB_off;
                const uint32_t a = st + r * 128 + ((uB ^ (r & 7)) * 16);
                uint32_t kbh[4], kbl[4];
                ldsm4(kbh[0], kbh[1], kbh[2], kbh[3], a);
                ldsm4(kbl[0], kbl[1], kbl[2], kbl[3], a + 8192);
                mma16816(accs[2*bn],   qfh[t], kbh[0], kbh[1]);
                mma16816(accs[2*bn],   qfh[t], kbl[0], kbl[1]);
                mma16816(accs[2*bn],   qfl[t], kbh[0], kbh[1]);
                mma16816(accs[2*bn+1], qfh[t], kbh[2], kbh[3]);
                mma16816(accs[2*bn+1], qfh[t], kbl[2], kbl[3]);
                mma16816(accs[2*bn+1], qfl[t], kbh[2], kbh[3]);
            }
        }
        #pragma unroll
        for (int nt = 0; nt < 8; nt++)
            #pragma unroll
            for (int e = 0; e < 4; e++) accs[nt][e] *= 0.125f;

        if (kv0 + AKV - 1 > q0 + wid * 16) {
            #pragma unroll
            for (int nt = 0; nt < 8; nt++)
                #pragma unroll
                for (int e = 0; e < 4; e++) {
                    const int row = q0 + wid * 16 + (lane >> 2) + ((e >> 1) ? 8 : 0);
                    const int col = kv0 + nt * 8 + 2 * (lane & 3) + (e & 1);
                    if (col > row) accs[nt][e] = -1e30f;
                }
        }

        #pragma unroll
        for (int h = 0; h < 2; h++) {
            float rm = -1e30f;
            #pragma unroll
            for (int nt = 0; nt < 8; nt++)
                rm = fmaxf(rm, fmaxf(accs[nt][2*h], accs[nt][2*h+1]));
            rm = fmaxf(rm, __shfl_xor_sync(0xffffffffu, rm, 1));
            rm = fmaxf(rm, __shfl_xor_sync(0xffffffffu, rm, 2));
            const float mnew = fmaxf(m_i[h], rm);
            const float corr = __expf(m_i[h] - mnew);
            m_i[h] = mnew;
            float rs = 0.f;
            #pragma unroll
            for (int nt = 0; nt < 8; nt++) {
                accs[nt][2*h]   = __expf(accs[nt][2*h]   - mnew);
                accs[nt][2*h+1] = __expf(accs[nt][2*h+1] - mnew);
                rs += accs[nt][2*h] + accs[nt][2*h+1];
            }
            rs += __shfl_xor_sync(0xffffffffu, rs, 1);
            rs += __shfl_xor_sync(0xffffffffu, rs, 2);
            l_i[h] = l_i[h] * corr + rs;
            #pragma unroll
            for (int nt = 0; nt < 8; nt++) {
                acc_o[nt][2*h]   *= corr;
                acc_o[nt][2*h+1] *= corr;
            }
        }

        uint32_t pfh[4][4], pfl[4][4];
        #pragma unroll
        for (int t = 0; t < 4; t++) {
            #pragma unroll
            for (int half = 0; half < 2; half++) {
                const int nt = 2 * t + half;
                __nv_bfloat16 h0, l0, h1, l1, h2, l2, h3, l3;
                split_bf16(accs[nt][0], h0, l0);
                split_bf16(accs[nt][1], h1, l1);
                split_bf16(accs[nt][2], h2, l2);
                split_bf16(accs[nt][3], h3, l3);
                pfh[t][half*2+0] = pack_bf16(h0, h1);
                pfh[t][half*2+1] = pack_bf16(h2, h3);
                pfl[t][half*2+0] = pack_bf16(l0, l1);
                pfl[t][half*2+1] = pack_bf16(l2, l3);
            }
        }

        #pragma unroll
        for (int t = 0; t < 4; t++) {
            #pragma unroll
            for (int bn = 0; bn < 4; bn++) {
                const int r = t * 16 + rowA_off;
                const int u = bn * 2 + (g >> 1);
                const uint32_t a = st + SV_OFF + r * 128 + ((u ^ (r & 7)) * 16);
                uint32_t vbh[4], vbl[4];
                ldsm4t(vbh[0], vbh[1], vbh[2], vbh[3], a);
                ldsm4t(vbl[0], vbl[1], vbl[2], vbl[3], a + 8192);
                mma16816(acc_o[2*bn],   pfh[t], vbh[0], vbh[1]);
                mma16816(acc_o[2*bn],   pfh[t], vbl[0], vbl[1]);
                mma16816(acc_o[2*bn],   pfl[t], vbh[0], vbh[1]);
                mma16816(acc_o[2*bn+1], pfh[t], vbh[2], vbh[3]);
                mma16816(acc_o[2*bn+1], pfh[t], vbl[2], vbl[3]);
                mma16816(acc_o[2*bn+1], pfl[t], vbh[2], vbh[3]);
            }
        }
    }

    const int bI = bh / HH;
    const int hI = bh % HH;
    #pragma unroll
    for (int h = 0; h < 2; h++) {
        const float inv = 1.0f / l_i[h];
        const int sI = q0 + wid * 16 + (lane >> 2) + h * 8;
        const size_t base = ((size_t)bI * SS + sI) * EE + hI * HD;
        #pragma unroll
        for (int nt = 0; nt < 8; nt++) {
            const int d = nt * 8 + 2 * (lane & 3);
            __nv_bfloat16 h0, l0, h1, l1;
            split_bf16(acc_o[nt][2*h]   * inv, h0, l0);
            split_bf16(acc_o[nt][2*h+1] * inv, h1, l1);
            *(uint32_t*)(Oh + base + d) = pack_bf16(h0, h1);
            *(uint32_t*)(Ol + base + d) = pack_bf16(l0, l1);
        }
    }
}

// ---------------- launch ----------------------------------------------------
extern "C" void kernel_launch(void* const* d_in, const int* in_sizes, int n_in,
                              void* d_out, int out_size)
{
    const float* x     = (const float*)d_in[0];
    const float* ln1_g = (const float*)d_in[1];
    const float* ln1_b = (const float*)d_in[2];
    const float* ln2_g = (const float*)d_in[3];
    const float* ln2_b = (const float*)d_in[4];
    const float* w_qkv = (const float*)d_in[5];
    const float* b_qkv = (const float*)d_in[6];
    const float* w_ao  = (const float*)d_in[7];
    const float* b_ao  = (const float*)d_in[8];
    const float* w_fc  = (const float*)d_in[9];
    const float* b_fc  = (const float*)d_in[10];
    const float* w_po  = (const float*)d_in[11];
    const float* b_po  = (const float*)d_in[12];
    float* out = (float*)d_out;

    float *x1;
    __nv_bfloat16 *qh, *ql, *kh, *kl, *vh, *vl;
    __nv_bfloat16 *lnh, *lnl, *ath, *atl, *acth, *actl;
    __nv_bfloat16 *wqh, *wql, *waoh, *waol, *wfh, *wfl, *wph, *wpl;
    cudaGetSymbolAddress((void**)&x1,  g_x1);
    cudaGetSymbolAddress((void**)&qh,  g_qh);
    cudaGetSymbolAddress((void**)&ql,  g_ql);
    cudaGetSymbolAddress((void**)&kh,  g_kh);
    cudaGetSymbolAddress((void**)&kl,  g_kl);
    cudaGetSymbolAddress((void**)&vh,  g_vh);
    cudaGetSymbolAddress((void**)&vl,  g_vl);
    cudaGetSymbolAddress((void**)&lnh, g_ln_hi);
    cudaGetSymbolAddress((void**)&lnl, g_ln_lo);
    cudaGetSymbolAddress((void**)&ath, g_at_hi);
    cudaGetSymbolAddress((void**)&atl, g_at_lo);
    cudaGetSymbolAddress((void**)&acth, g_act_hi);
    cudaGetSymbolAddress((void**)&actl, g_act_lo);
    cudaGetSymbolAddress((void**)&wqh, g_wqkv_hi);
    cudaGetSymbolAddress((void**)&wql, g_wqkv_lo);
    cudaGetSymbolAddress((void**)&waoh, g_wao_hi);
    cudaGetSymbolAddress((void**)&waol, g_wao_lo);
    cudaGetSymbolAddress((void**)&wfh, g_wfc_hi);
    cudaGetSymbolAddress((void**)&wfl, g_wfc_lo);
    cudaGetSymbolAddress((void**)&wph, g_wpo_hi);
    cudaGetSymbolAddress((void**)&wpl, g_wpo_lo);

    cudaFuncSetAttribute(attn_mma,     cudaFuncAttributeMaxDynamicSharedMemorySize, ATTN_SMEM);
    cudaFuncSetAttribute(hmma_gemm<0>, cudaFuncAttributeMaxDynamicSharedMemorySize, GEMM_SMEM);
    cudaFuncSetAttribute(hmma_gemm<1>, cudaFuncAttributeMaxDynamicSharedMemorySize, GEMM_SMEM);
    cudaFuncSetAttribute(hmma_gemm<3>, cudaFuncAttributeMaxDynamicSharedMemorySize, GEMM_SMEM);
    cudaFuncSetAttribute(hmma_gemm_fc, cudaFuncAttributeMaxDynamicSharedMemorySize, GEMM2_SMEM);

    // fused weight conversion + LN1 (single launch)
    cvt_ln1_kernel<<<CVT_BLOCKS + MM, 256>>>(w_qkv, w_ao, w_fc, w_po, x, ln1_g, ln1_b);

    // 2. QKV GEMM (M=4096, N=3072, K=1024), emit Q/K/V hi-lo [B,H,S,HD]
    hmma_gemm<0><<<dim3(3*EE/BN, MM/BM), GT, GEMM_SMEM>>>(
        lnh, lnl, wqh, wql, b_qkv, nullptr, nullptr, 3*EE, EE);
    // 3. HMMA causal flash attention (LPT order) -> at hi/lo
    attn_mma<<<dim3(SS/AQ, BB*HH), 256, ATTN_SMEM>>>(qh, ql, kh, kl, vh, vl, ath, atl);
    // 4. AO GEMM + residual -> x1 (fp32)
    hmma_gemm<1><<<dim3(EE/BN, MM/BM), GT, GEMM_SMEM>>>(
        ath, atl, waoh, waol, b_ao, x, x1, EE, EE);
    // 5. LN2 -> hi/lo
    ln_kernel<<<MM, 256>>>(x1, ln2_g, ln2_b, lnh, lnl);
    // 6. FC GEMM + gelu -> act hi/lo (128x128 tiles: 1024 CTAs, 1.2% quant waste)
    hmma_gemm_fc<<<dim3(DFF/BN2, MM/BM2), GT, GEMM2_SMEM>>>(
        lnh, lnl, wfh, wfl, b_fc, DFF, EE);
    // 7. PO GEMM + residual -> out
    hmma_gemm<3><<<dim3(EE/BN, MM/BM), GT, GEMM_SMEM>>>(
        acth, actl, wph, wpl, b_po, x1, out, EE, DFF);
}

// round 17
// speedup vs baseline: 1.0835x; 1.0184x over previous
#include <cuda_runtime.h>
#include <cuda_bf16.h>
#include <math.h>
#include <stdint.h>

// Problem constants
#define BB   2
#define SS   2048
#define EE   1024
#define HH   16
#define HD   64
#define DFF  4096
#define MM   (BB*SS)   // 4096 tokens

// ---------------- scratch (device globals; no allocations allowed) ----------
__device__ __align__(128) float g_x1[(size_t)MM*EE];     // residual after attn

__device__ __align__(128) __nv_bfloat16 g_qh [(size_t)MM*EE],  g_ql [(size_t)MM*EE];  // [B,H,S,HD]
__device__ __align__(128) __nv_bfloat16 g_kh [(size_t)MM*EE],  g_kl [(size_t)MM*EE];  // [B,H,S,HD]
__device__ __align__(128) __nv_bfloat16 g_vh [(size_t)MM*EE],  g_vl [(size_t)MM*EE];  // [B,H,S,HD]

__device__ __align__(128) __nv_bfloat16 g_ln_hi [(size_t)MM*EE],  g_ln_lo [(size_t)MM*EE];
__device__ __align__(128) __nv_bfloat16 g_at_hi [(size_t)MM*EE],  g_at_lo [(size_t)MM*EE];
__device__ __align__(128) __nv_bfloat16 g_act_hi[(size_t)MM*DFF], g_act_lo[(size_t)MM*DFF];

__device__ __align__(128) __nv_bfloat16 g_wqkv_hi[(size_t)3*EE*EE], g_wqkv_lo[(size_t)3*EE*EE];
__device__ __align__(128) __nv_bfloat16 g_wao_hi [(size_t)EE*EE],   g_wao_lo [(size_t)EE*EE];
__device__ __align__(128) __nv_bfloat16 g_wfc_hi [(size_t)DFF*EE],  g_wfc_lo [(size_t)DFF*EE];
__device__ __align__(128) __nv_bfloat16 g_wpo_hi [(size_t)EE*DFF],  g_wpo_lo [(size_t)EE*DFF];

// ---------------- helpers ----------------------------------------------------
__device__ __forceinline__ uint32_t smem_u32(const void* p) {
    uint32_t a;
    asm("{ .reg .u64 t; cvta.to.shared.u64 t, %1; cvt.u32.u64 %0, t; }"
        : "=r"(a) : "l"(p));
    return a;
}
__device__ __forceinline__ void cp16(uint32_t saddr, const void* gptr) {
    asm volatile("cp.async.cg.shared.global [%0], [%1], 16;"
                 :: "r"(saddr), "l"(gptr));
}
__device__ __forceinline__ void cp_commit() {
    asm volatile("cp.async.commit_group;" ::: "memory");
}
__device__ __forceinline__ void cp_wait0() {
    asm volatile("cp.async.wait_group 0;" ::: "memory");
}
__device__ __forceinline__ void ldsm4(uint32_t& r0, uint32_t& r1, uint32_t& r2,
                                      uint32_t& r3, uint32_t addr) {
    asm volatile("ldmatrix.sync.aligned.m8n8.x4.shared.b16 {%0,%1,%2,%3}, [%4];"
                 : "=r"(r0), "=r"(r1), "=r"(r2), "=r"(r3) : "r"(addr));
}
__device__ __forceinline__ void ldsm4t(uint32_t& r0, uint32_t& r1, uint32_t& r2,
                                       uint32_t& r3, uint32_t addr) {
    asm volatile("ldmatrix.sync.aligned.m8n8.x4.trans.shared.b16 {%0,%1,%2,%3}, [%4];"
                 : "=r"(r0), "=r"(r1), "=r"(r2), "=r"(r3) : "r"(addr));
}
__device__ __forceinline__ void mma16816(float* c, const uint32_t* a,
                                         uint32_t b0, uint32_t b1) {
    asm volatile(
        "mma.sync.aligned.m16n8k16.row.col.f32.bf16.bf16.f32 "
        "{%0,%1,%2,%3}, {%4,%5,%6,%7}, {%8,%9}, {%0,%1,%2,%3};"
        : "+f"(c[0]), "+f"(c[1]), "+f"(c[2]), "+f"(c[3])
        : "r"(a[0]), "r"(a[1]), "r"(a[2]), "r"(a[3]), "r"(b0), "r"(b1));
}

__device__ __forceinline__ float gelu_tanh(float x) {
    const float c = 0.7978845608028654f;
    const float u = c * (x + 0.044715f * x * x * x);
    const float t = 1.0f - 2.0f / (1.0f + __expf(2.0f * u));
    return 0.5f * x * (1.0f + t);
}
__device__ __forceinline__ void split_bf16(float v, __nv_bfloat16& h, __nv_bfloat16& l) {
    h = __float2bfloat16(v);
    l = __float2bfloat16(v - __bfloat162float(h));
}
__device__ __forceinline__ uint32_t pack_bf16(__nv_bfloat16 a, __nv_bfloat16 b) {
    uint16_t ua = *reinterpret_cast<uint16_t*>(&a);
    uint16_t ub = *reinterpret_cast<uint16_t*>(&b);
    return (uint32_t)ua | ((uint32_t)ub << 16);
}

// ---------------- LayerNorm row body ------------------------------------------
__device__ __forceinline__ void ln_row(
    const float* __restrict__ x, const float* __restrict__ g,
    const float* __restrict__ b, __nv_bfloat16* __restrict__ oh,
    __nv_bfloat16* __restrict__ ol, int row)
{
    const int t = threadIdx.x;
    const float4 v = ((const float4*)(x + (size_t)row * EE))[t];

    float s  = v.x + v.y + v.z + v.w;
    float ss = v.x*v.x + v.y*v.y + v.z*v.z + v.w*v.w;

    __shared__ float ws[8], wss[8];
    __shared__ float s_mu, s_rstd;
    const unsigned lane = t & 31u, w = t >> 5;
    #pragma unroll
    for (int off = 16; off; off >>= 1) {
        s  += __shfl_down_sync(0xffffffffu, s,  off);
        ss += __shfl_down_sync(0xffffffffu, ss, off);
    }
    if (lane == 0) { ws[w] = s; wss[w] = ss; }
    __syncthreads();
    if (t == 0) {
        float ts = 0.f, tss = 0.f;
        #pragma unroll
        for (int i = 0; i < 8; i++) { ts += ws[i]; tss += wss[i]; }
        const float mu  = ts * (1.0f / EE);
        const float var = tss * (1.0f / EE) - mu * mu;
        s_mu = mu; s_rstd = rsqrtf(var + 1e-5f);
    }
    __syncthreads();
    const float mu = s_mu, rstd = s_rstd;
    const float4 gg = ((const float4*)g)[t];
    const float4 bb = ((const float4*)b)[t];
    float o0 = (v.x - mu)*rstd*gg.x + bb.x;
    float o1 = (v.y - mu)*rstd*gg.y + bb.y;
    float o2 = (v.z - mu)*rstd*gg.z + bb.z;
    float o3 = (v.w - mu)*rstd*gg.w + bb.w;
    const size_t base = (size_t)row * EE + t * 4;
    __nv_bfloat16 h, l;
    split_bf16(o0, h, l); oh[base+0] = h; ol[base+0] = l;
    split_bf16(o1, h, l); oh[base+1] = h; ol[base+1] = l;
    split_bf16(o2, h, l); oh[base+2] = h; ol[base+2] = l;
    split_bf16(o3, h, l); oh[base+3] = h; ol[base+3] = l;
}

__global__ __launch_bounds__(256) void ln_kernel(
    const float* __restrict__ x, const float* __restrict__ g,
    const float* __restrict__ b, __nv_bfloat16* __restrict__ oh,
    __nv_bfloat16* __restrict__ ol)
{
    ln_row(x, g, b, oh, ol, blockIdx.x);
}

// ---------------- fused weight cvt + LN1 (single launch) ---------------------
#define N4_QKV  (3*EE*EE/4)
#define N4_AO   (EE*EE/4)
#define N4_FC   (DFF*EE/4)
#define N4_PO   (EE*DFF/4)
#define N4_ALL  (N4_QKV + N4_AO + N4_FC + N4_PO)
#define CVT_BLOCKS ((N4_ALL + 255) / 256)

__global__ __launch_bounds__(256) void cvt_ln1_kernel(
    const float* __restrict__ s_qkv, const float* __restrict__ s_ao,
    const float* __restrict__ s_fc,  const float* __restrict__ s_po,
    const float* __restrict__ x, const float* __restrict__ ln1_g,
    const float* __restrict__ ln1_b)
{
    if (blockIdx.x >= CVT_BLOCKS) {
        ln_row(x, ln1_g, ln1_b, g_ln_hi, g_ln_lo, blockIdx.x - CVT_BLOCKS);
        return;
    }
    int i = blockIdx.x * 256 + threadIdx.x;
    if (i >= N4_ALL) return;
    const float* src;
    __nv_bfloat16 *hi, *lo;
    if (i < N4_QKV)                      { src = s_qkv; hi = g_wqkv_hi; lo = g_wqkv_lo; }
    else if (i < N4_QKV + N4_AO)         { i -= N4_QKV; src = s_ao; hi = g_wao_hi; lo = g_wao_lo; }
    else if (i < N4_QKV + N4_AO + N4_FC) { i -= N4_QKV + N4_AO; src = s_fc; hi = g_wfc_hi; lo = g_wfc_lo; }
    else                                 { i -= N4_QKV + N4_AO + N4_FC; src = s_po; hi = g_wpo_hi; lo = g_wpo_lo; }
    const float4 v = ((const float4*)src)[i];
    __nv_bfloat16 h, l;
    const size_t base = (size_t)i * 4;
    split_bf16(v.x, h, l); hi[base+0] = h; lo[base+0] = l;
    split_bf16(v.y, h, l); hi[base+1] = h; lo[base+1] = l;
    split_bf16(v.z, h, l); hi[base+2] = h; lo[base+2] = l;
    split_bf16(v.w, h, l); hi[base+3] = h; lo[base+3] = l;
}

// ---------------- HMMA bf16x3 GEMM, 256x128 tiles (QKV / AO / PO) ------------
#define BM 256
#define BN 128
#define BK 64
#define GT 256
#define STAGE_BYTES 98304
#define SOFF_B 65536
#define GEMM_SMEM (2*STAGE_BYTES) // 196608

template<int MODE>
__global__ __launch_bounds__(GT, 1)
void hmma_gemm(const __nv_bfloat16* __restrict__ Ah, const __nv_bfloat16* __restrict__ Al,
               const __nv_bfloat16* __restrict__ Wh, const __nv_bfloat16* __restrict__ Wl,
               const float* __restrict__ bias, const float* __restrict__ res,
               float* __restrict__ out, int N, int K)
{
    extern __shared__ char smem[];
    const uint32_t sb = smem_u32(smem);
    const int tid  = threadIdx.x;
    const int wid  = tid >> 5;
    const int lane = tid & 31;
    const int m0 = blockIdx.y * BM, n0 = blockIdx.x * BN;
    const int warp_m0 = (wid & 3) * 64;
    const int warp_n0 = (wid >> 2) * 64;

    const int nch = K / BK;

    auto load_chunk = [&](int stage, int k0) {
        #pragma unroll
        for (int qq = 0; qq < 24; qq++) {
            const int it = tid + qq * GT;
            uint32_t soff;
            const __nv_bfloat16* gp;
            if (it < 4096) {                    // A (256 rows x 64)
                const int hl  = it >> 11;
                const int idx = it & 2047;
                const int r   = idx >> 3;
                const int u   = idx & 7;
                gp = (hl ? Al : Ah) + (size_t)(m0 + r) * K + k0 + u * 8;
                soff = stage * STAGE_BYTES + hl * 32768 + r * 128 +
                       ((u ^ (r & 7)) * 16);
            } else {                            // B (128 rows x 64)
                const int it2 = it - 4096;
                const int hl  = it2 >> 10;
                const int idx = it2 & 1023;
                const int r   = idx >> 3;
                const int u   = idx & 7;
                gp = (hl ? Wl : Wh) + (size_t)(n0 + r) * K + k0 + u * 8;
                soff = stage * STAGE_BYTES + SOFF_B + hl * 16384 + r * 128 +
                       ((u ^ (r & 7)) * 16);
            }
            cp16(sb + soff, gp);
        }
    };

    float acc[4][8][4];
    #pragma unroll
    for (int i = 0; i < 4; i++)
        #pragma unroll
        for (int j = 0; j < 8; j++)
            #pragma unroll
            for (int e = 0; e < 4; e++) acc[i][j][e] = 0.f;

    load_chunk(0, 0);   cp_commit();

    const int g  = lane >> 3;
    const int tg = lane & 7;
    const int rowA_off = (g & 1) * 8 + tg;
    const int rowB_off = (g >> 1) * 8 + tg;

    for (int c = 0; c < nch; c++) {
        cp_wait0();
        __syncthreads();
        if (c + 1 < nch) load_chunk((c + 1) & 1, (c + 1) * BK);
        cp_commit();

        const uint32_t stA = sb + (c & 1) * STAGE_BYTES;
        const uint32_t stB = stA + SOFF_B;

        #pragma unroll
        for (int kk = 0; kk < 4; kk++) {
            uint32_t ah[4][4], al[4][4];
            const int unitA = kk * 2 + (g >> 1);
            #pragma unroll
            for (int tm = 0; tm < 4; tm++) {
                const int r = warp_m0 + tm * 16 + rowA_off;
                const uint32_t a = stA + r * 128 + ((unitA ^ (r & 7)) * 16);
                ldsm4(ah[tm][0], ah[tm][1], ah[tm][2], ah[tm][3], a);
                ldsm4(al[tm][0], al[tm][1], al[tm][2], al[tm][3], a + 32768);
            }
            const int unitB = kk * 2 + (g & 1);
            #pragma unroll
            for (int bn = 0; bn < 4; bn++) {
                const int r = warp_n0 + bn * 16 + rowB_off;
                const uint32_t a = stB + r * 128 + ((unitB ^ (r & 7)) * 16);
                uint32_t bh[4], bl[4];
                ldsm4(bh[0], bh[1], bh[2], bh[3], a);
                ldsm4(bl[0], bl[1], bl[2], bl[3], a + 16384);
                #pragma unroll
                for (int tm = 0; tm < 4; tm++) {
                    mma16816(acc[tm][2*bn],   ah[tm], bh[0], bh[1]);
                    mma16816(acc[tm][2*bn],   ah[tm], bl[0], bl[1]);
                    mma16816(acc[tm][2*bn],   al[tm], bh[0], bh[1]);
                    mma16816(acc[tm][2*bn+1], ah[tm], bh[2], bh[3]);
                    mma16816(acc[tm][2*bn+1], ah[tm], bl[2], bl[3]);
                    mma16816(acc[tm][2*bn+1], al[tm], bh[2], bh[3]);
                }
            }
        }
    }

    // ---- epilogue ----
    const int r_lo = lane >> 2;
    const int c_lo = (lane & 3) * 2;
    #pragma unroll
    for (int tm = 0; tm < 4; tm++) {
        #pragma unroll
        for (int tn = 0; tn < 8; tn++) {
            const int n = n0 + warp_n0 + tn * 8 + c_lo;
            #pragma unroll
            for (int h = 0; h < 2; h++) {
                const int m = m0 + warp_m0 + tm * 16 + r_lo + h * 8;
                float v0 = acc[tm][tn][h * 2 + 0] + bias[n];
                float v1 = acc[tm][tn][h * 2 + 1] + bias[n + 1];
                if (MODE == 0) {
                    const int head  = n / (3 * HD);
                    const int rem   = n % (3 * HD);
                    const int which = rem / HD;
                    const int d     = rem % HD;
                    const int bI    = m / SS;
                    const int sI    = m % SS;
                    __nv_bfloat16 h0, l0, h1, l1;
                    split_bf16(v0, h0, l0);
                    split_bf16(v1, h1, l1);
                    const size_t dst = (((size_t)bI * HH + head) * SS + sI) * HD + d;
                    __nv_bfloat16* ph = (which == 0) ? g_qh : (which == 1) ? g_kh : g_vh;
                    __nv_bfloat16* pl = (which == 0) ? g_ql : (which == 1) ? g_kl : g_vl;
                    *(uint32_t*)(ph + dst) = pack_bf16(h0, h1);
                    *(uint32_t*)(pl + dst) = pack_bf16(l0, l1);
                } else { // MODE 1 / 3: +bias +residual -> fp32
                    const size_t o = (size_t)m * N + n;
                    const float2 rr = *(const float2*)(res + o);
                    float2 ov; ov.x = v0 + rr.x; ov.y = v1 + rr.y;
                    *(float2*)(out + o) = ov;
                }
            }
        }
    }
}

// ---------------- HMMA bf16x3 GEMM, 128x128 tiles (FC, gelu epilogue) --------
#define BM2 128
#define BN2 128
#define STAGE2_BYTES 65536
#define S2OFF_B 32768
#define GEMM2_SMEM (2*STAGE2_BYTES) // 131072

__global__ __launch_bounds__(GT, 1)
void hmma_gemm_fc(const __nv_bfloat16* __restrict__ Ah, const __nv_bfloat16* __restrict__ Al,
                  const __nv_bfloat16* __restrict__ Wh, const __nv_bfloat16* __restrict__ Wl,
                  const float* __restrict__ bias, int N, int K)
{
    extern __shared__ char smem[];
    const uint32_t sb = smem_u32(smem);
    const int tid  = threadIdx.x;
    const int wid  = tid >> 5;
    const int lane = tid & 31;
    const int m0 = blockIdx.y * BM2, n0 = blockIdx.x * BN2;
    const int warp_m0 = (wid & 1) * 64;
    const int warp_n0 = (wid >> 1) * 32;

    const int nch = K / BK;

    auto load_chunk = [&](int stage, int k0) {
        #pragma unroll
        for (int qq = 0; qq < 16; qq++) {
            const int it = tid + qq * GT;
            const int half = it >> 11;
            const int hl   = (it >> 10) & 1;
            const int idx  = it & 1023;
            const int r    = idx >> 3;
            const int u    = idx & 7;
            const __nv_bfloat16* gp = half
                ? ((hl ? Wl : Wh) + (size_t)(n0 + r) * K + k0 + u * 8)
                : ((hl ? Al : Ah) + (size_t)(m0 + r) * K + k0 + u * 8);
            const uint32_t soff = stage * STAGE2_BYTES + half * S2OFF_B +
                                  hl * 16384 + r * 128 + ((u ^ (r & 7)) * 16);
            cp16(sb + soff, gp);
        }
    };

    float acc[4][4][4];
    #pragma unroll
    for (int i = 0; i < 4; i++)
        #pragma unroll
        for (int j = 0; j < 4; j++)
            #pragma unroll
            for (int e = 0; e < 4; e++) acc[i][j][e] = 0.f;

    load_chunk(0, 0);   cp_commit();

    const int g  = lane >> 3;
    const int tg = lane & 7;
    const int rowA_off = (g & 1) * 8 + tg;
    const int rowB_off = (g >> 1) * 8 + tg;

    for (int c = 0; c < nch; c++) {
        cp_wait0();
        __syncthreads();
        if (c + 1 < nch) load_chunk((c + 1) & 1, (c + 1) * BK);
        cp_commit();

        const uint32_t stA = sb + (c & 1) * STAGE2_BYTES;
        const uint32_t stB = stA + S2OFF_B;

        #pragma unroll
        for (int kk = 0; kk < 4; kk++) {
            uint32_t ah[4][4], al[4][4];
            const int unitA = kk * 2 + (g >> 1);
            #pragma unroll
            for (int tm = 0; tm < 4; tm++) {
                const int r = warp_m0 + tm * 16 + rowA_off;
                const uint32_t a = stA + r * 128 + ((unitA ^ (r & 7)) * 16);
                ldsm4(ah[tm][0], ah[tm][1], ah[tm][2], ah[tm][3], a);
                ldsm4(al[tm][0], al[tm][1], al[tm][2], al[tm][3], a + 16384);
            }
            const int unitB = kk * 2 + (g & 1);
            #pragma unroll
            for (int bn = 0; bn < 2; bn++) {
                const int r = warp_n0 + bn * 16 + rowB_off;
                const uint32_t a = stB + r * 128 + ((unitB ^ (r & 7)) * 16);
                uint32_t bh[4], bl[4];
                ldsm4(bh[0], bh[1], bh[2], bh[3], a);
                ldsm4(bl[0], bl[1], bl[2], bl[3], a + 16384);
                #pragma unroll
                for (int tm = 0; tm < 4; tm++) {
                    mma16816(acc[tm][2*bn],   ah[tm], bh[0], bh[1]);
                    mma16816(acc[tm][2*bn],   ah[tm], bl[0], bl[1]);
                    mma16816(acc[tm][2*bn],   al[tm], bh[0], bh[1]);
                    mma16816(acc[tm][2*bn+1], ah[tm], bh[2], bh[3]);
                    mma16816(acc[tm][2*bn+1], ah[tm], bl[2], bl[3]);
                    mma16816(acc[tm][2*bn+1], al[tm], bh[2], bh[3]);
                }
            }
        }
    }

    // ---- epilogue: gelu -> hi/lo bf16 ----
    const int r_lo = lane >> 2;
    const int c_lo = (lane & 3) * 2;
    #pragma unroll
    for (int tm = 0; tm < 4; tm++) {
        #pragma unroll
        for (int tn = 0; tn < 4; tn++) {
            const int n = n0 + warp_n0 + tn * 8 + c_lo;
            #pragma unroll
            for (int h = 0; h < 2; h++) {
                const int m = m0 + warp_m0 + tm * 16 + r_lo + h * 8;
                float v0 = acc[tm][tn][h * 2 + 0] + bias[n];
                float v1 = acc[tm][tn][h * 2 + 1] + bias[n + 1];
                const size_t o = (size_t)m * N + n;
                __nv_bfloat16 hh, ll;
                split_bf16(gelu_tanh(v0), hh, ll); g_act_hi[o]   = hh; g_act_lo[o]   = ll;
                split_bf16(gelu_tanh(v1), hh, ll); g_act_hi[o+1] = hh; g_act_lo[o+1] = ll;
            }
        }
    }
}

// ---------------- HMMA flash attention (causal, LPT, 2 CTAs/SM) ---------------
// AQ=64, 4 warps / 128 threads, smem 80K -> two CTAs co-resident per SM so one
// CTA's MMAs overlap the other's softmax. Per-warp structure unchanged.
#define AQ  64
#define AKV 64
#define SQ_H 0
#define SQ_L 8192
#define SST(s) (16384 + (s)*32768)
#define SV_OFF 16384
#define ATTN_SMEM 81920
#define AT 128

__global__ __launch_bounds__(AT, 2) void attn_mma(
    const __nv_bfloat16* __restrict__ Qh, const __nv_bfloat16* __restrict__ Ql,
    const __nv_bfloat16* __restrict__ Kh, const __nv_bfloat16* __restrict__ Kl,
    const __nv_bfloat16* __restrict__ Vh, const __nv_bfloat16* __restrict__ Vl,
    __nv_bfloat16* __restrict__ Oh, __nv_bfloat16* __restrict__ Ol)
{
    extern __shared__ char smem[];
    const uint32_t sb = smem_u32(smem);
    const int tid  = threadIdx.x;
    const int wid  = tid >> 5;          // 0..3
    const int lane = tid & 31;
    const int bh   = blockIdx.y;
    const int qblk = gridDim.x - 1 - blockIdx.x;   // heavy blocks first (LPT)
    const int q0   = qblk * AQ;
    const int g  = lane >> 3;
    const int tg = lane & 7;

    const __nv_bfloat16* Qhb = Qh + (size_t)bh * SS * HD;
    const __nv_bfloat16* Qlb = Ql + (size_t)bh * SS * HD;
    const __nv_bfloat16* Khb = Kh + (size_t)bh * SS * HD;
    const __nv_bfloat16* Klb = Kl + (size_t)bh * SS * HD;
    const __nv_bfloat16* Vhb = Vh + (size_t)bh * SS * HD;
    const __nv_bfloat16* Vlb = Vl + (size_t)bh * SS * HD;

    // ---- Q tile load (hi/lo, 64x64, swizzled) ----
    #pragma unroll
    for (int qq = 0; qq < 8; qq++) {
        const int it = tid + qq * AT;      // 0..1023
        const int hl = it >> 9;
        const int r  = (it >> 3) & 63;
        const int u  = it & 7;
        const __nv_bfloat16* src = (hl ? Qlb : Qhb) + (size_t)(q0 + r) * HD + u * 8;
        cp16(sb + (hl ? SQ_L : SQ_H) + r * 128 + ((u ^ (r & 7)) * 16), src);
    }

    const int nkv = qblk + 1;

    auto load_kv = [&](int stage, int kv0) {
        #pragma unroll
        for (int qq = 0; qq < 16; qq++) {
            const int it  = tid + qq * AT;   // 0..2047
            const int mat = it >> 9;
            const int r   = (it >> 3) & 63;
            const int u   = it & 7;
            const __nv_bfloat16* src;
            if (mat == 0)      src = Khb + (size_t)(kv0 + r) * HD + u * 8;
            else if (mat == 1) src = Klb + (size_t)(kv0 + r) * HD + u * 8;
            else if (mat == 2) src = Vhb + (size_t)(kv0 + r) * HD + u * 8;
            else               src = Vlb + (size_t)(kv0 + r) * HD + u * 8;
            cp16(sb + SST(stage) + mat * 8192 + r * 128 + ((u ^ (r & 7)) * 16), src);
        }
    };

    load_kv(0, 0);
    cp_commit();
    cp_wait0();
    __syncthreads();

    uint32_t qfh[4][4], qfl[4][4];
    const int rowA_off = (g & 1) * 8 + tg;
    {
        #pragma unroll
        for (int t = 0; t < 4; t++) {
            const int r  = wid * 16 + rowA_off;
            const int uA = t * 2 + (g >> 1);
            const uint32_t a = sb + SQ_H + r * 128 + ((uA ^ (r & 7)) * 16);
            ldsm4(qfh[t][0], qfh[t][1], qfh[t][2], qfh[t][3], a);
            ldsm4(qfl[t][0], qfl[t][1], qfl[t][2], qfl[t][3], a + 8192);
        }
    }

    float m_i[2] = {-1e30f, -1e30f};
    float l_i[2] = {0.f, 0.f};
    float acc_o[8][4];
    #pragma unroll
    for (int nt = 0; nt < 8; nt++)
        #pragma unroll
        for (int e = 0; e < 4; e++) acc_o[nt][e] = 0.f;

    const int rowB_off = (g >> 1) * 8 + tg;

    for (int j = 0; j < nkv; j++) {
        const int kv0 = j * AKV;
        if (j > 0) { cp_wait0(); __syncthreads(); }
        if (j + 1 < nkv) { load_kv((j + 1) & 1, (j + 1) * AKV); cp_commit(); }

        const uint32_t st = sb + SST(j & 1);

        float accs[8][4];
        #pragma unroll
        for (int nt = 0; nt < 8; nt++)
            #pragma unroll
            for (int e = 0; e < 4; e++) accs[nt][e] = 0.f;

        #pragma unroll
        for (int t = 0; t < 4; t++) {
            const int uB = t * 2 + (g & 1);
            #pragma unroll
            for (int bn = 0; bn < 4; bn++) {
                const int r = bn * 16 + rowB_off;
                const uint32_t a = st + r * 128 + ((uB ^ (r & 7)) * 16);
                uint32_t kbh[4], kbl[4];
                ldsm4(kbh[0], kbh[1], kbh[2], kbh[3], a);
                ldsm4(kbl[0], kbl[1], kbl[2], kbl[3], a + 8192);
                mma16816(accs[2*bn],   qfh[t], kbh[0], kbh[1]);
                mma16816(accs[2*bn],   qfh[t], kbl[0], kbl[1]);
                mma16816(accs[2*bn],   qfl[t], kbh[0], kbh[1]);
                mma16816(accs[2*bn+1], qfh[t], kbh[2], kbh[3]);
                mma16816(accs[2*bn+1], qfh[t], kbl[2], kbl[3]);
                mma16816(accs[2*bn+1], qfl[t], kbh[2], kbh[3]);
            }
        }
        #pragma unroll
        for (int nt = 0; nt < 8; nt++)
            #pragma unroll
            for (int e = 0; e < 4; e++) accs[nt][e] *= 0.125f;

        if (kv0 + AKV - 1 > q0 + wid * 16) {
            #pragma unroll
            for (int nt = 0; nt < 8; nt++)
                #pragma unroll
                for (int e = 0; e < 4; e++) {
                    const int row = q0 + wid * 16 + (lane >> 2) + ((e >> 1) ? 8 : 0);
                    const int col = kv0 + nt * 8 + 2 * (lane & 3) + (e & 1);
                    if (col > row) accs[nt][e] = -1e30f;
                }
        }

        #pragma unroll
        for (int h = 0; h < 2; h++) {
            float rm = -1e30f;
            #pragma unroll
            for (int nt = 0; nt < 8; nt++)
                rm = fmaxf(rm, fmaxf(accs[nt][2*h], accs[nt][2*h+1]));
            rm = fmaxf(rm, __shfl_xor_sync(0xffffffffu, rm, 1));
            rm = fmaxf(rm, __shfl_xor_sync(0xffffffffu, rm, 2));
            const float mnew = fmaxf(m_i[h], rm);
            const float corr = __expf(m_i[h] - mnew);
            m_i[h] = mnew;
            float rs = 0.f;
            #pragma unroll
            for (int nt = 0; nt < 8; nt++) {
                accs[nt][2*h]   = __expf(accs[nt][2*h]   - mnew);
                accs[nt][2*h+1] = __expf(accs[nt][2*h+1] - mnew);
                rs += accs[nt][2*h] + accs[nt][2*h+1];
            }
            rs += __shfl_xor_sync(0xffffffffu, rs, 1);
            rs += __shfl_xor_sync(0xffffffffu, rs, 2);
            l_i[h] = l_i[h] * corr + rs;
            #pragma unroll
            for (int nt = 0; nt < 8; nt++) {
                acc_o[nt][2*h]   *= corr;
                acc_o[nt][2*h+1] *= corr;
            }
        }

        uint32_t pfh[4][4], pfl[4][4];
        #pragma unroll
        for (int t = 0; t < 4; t++) {
            #pragma unroll
            for (int half = 0; half < 2; half++) {
                const int nt = 2 * t + half;
                __nv_bfloat16 h0, l0, h1, l1, h2, l2, h3, l3;
                split_bf16(accs[nt][0], h0, l0);
                split_bf16(accs[nt][1], h1, l1);
                split_bf16(accs[nt][2], h2, l2);
                split_bf16(accs[nt][3], h3, l3);
                pfh[t][half*2+0] = pack_bf16(h0, h1);
                pfh[t][half*2+1] = pack_bf16(h2, h3);
                pfl[t][half*2+0] = pack_bf16(l0, l1);
                pfl[t][half*2+1] = pack_bf16(l2, l3);
            }
        }

        #pragma unroll
        for (int t = 0; t < 4; t++) {
            #pragma unroll
            for (int bn = 0; bn < 4; bn++) {
                const int r = t * 16 + rowA_off;
                const int u = bn * 2 + (g >> 1);
                const uint32_t a = st + SV_OFF + r * 128 + ((u ^ (r & 7)) * 16);
                uint32_t vbh[4], vbl[4];
                ldsm4t(vbh[0], vbh[1], vbh[2], vbh[3], a);
                ldsm4t(vbl[0], vbl[1], vbl[2], vbl[3], a + 8192);
                mma16816(acc_o[2*bn],   pfh[t], vbh[0], vbh[1]);
                mma16816(acc_o[2*bn],   pfh[t], vbl[0], vbl[1]);
                mma16816(acc_o[2*bn],   pfl[t], vbh[0], vbh[1]);
                mma16816(acc_o[2*bn+1], pfh[t], vbh[2], vbh[3]);
                mma16816(acc_o[2*bn+1], pfh[t], vbl[2], vbl[3]);
                mma16816(acc_o[2*bn+1], pfl[t], vbh[2], vbh[3]);
            }
        }
    }

    const int bI = bh / HH;
    const int hI = bh % HH;
    #pragma unroll
    for (int h = 0; h < 2; h++) {
        const float inv = 1.0f / l_i[h];
        const int sI = q0 + wid * 16 + (lane >> 2) + h * 8;
        const size_t base = ((size_t)bI * SS + sI) * EE + hI * HD;
        #pragma unroll
        for (int nt = 0; nt < 8; nt++) {
            const int d = nt * 8 + 2 * (lane & 3);
            __nv_bfloat16 h0, l0, h1, l1;
            split_bf16(acc_o[nt][2*h]   * inv, h0, l0);
            split_bf16(acc_o[nt][2*h+1] * inv, h1, l1);
            *(uint32_t*)(Oh + base + d) = pack_bf16(h0, h1);
            *(uint32_t*)(Ol + base + d) = pack_bf16(l0, l1);
        }
    }
}

// ---------------- launch ----------------------------------------------------
extern "C" void kernel_launch(void* const* d_in, const int* in_sizes, int n_in,
                              void* d_out, int out_size)
{
    const float* x     = (const float*)d_in[0];
    const float* ln1_g = (const float*)d_in[1];
    const float* ln1_b = (const float*)d_in[2];
    const float* ln2_g = (const float*)d_in[3];
    const float* ln2_b = (const float*)d_in[4];
    const float* w_qkv = (const float*)d_in[5];
    const float* b_qkv = (const float*)d_in[6];
    const float* w_ao  = (const float*)d_in[7];
    const float* b_ao  = (const float*)d_in[8];
    const float* w_fc  = (const float*)d_in[9];
    const float* b_fc  = (const float*)d_in[10];
    const float* w_po  = (const float*)d_in[11];
    const float* b_po  = (const float*)d_in[12];
    float* out = (float*)d_out;

    float *x1;
    __nv_bfloat16 *qh, *ql, *kh, *kl, *vh, *vl;
    __nv_bfloat16 *lnh, *lnl, *ath, *atl, *acth, *actl;
    __nv_bfloat16 *wqh, *wql, *waoh, *waol, *wfh, *wfl, *wph, *wpl;
    cudaGetSymbolAddress((void**)&x1,  g_x1);
    cudaGetSymbolAddress((void**)&qh,  g_qh);
    cudaGetSymbolAddress((void**)&ql,  g_ql);
    cudaGetSymbolAddress((void**)&kh,  g_kh);
    cudaGetSymbolAddress((void**)&kl,  g_kl);
    cudaGetSymbolAddress((void**)&vh,  g_vh);
    cudaGetSymbolAddress((void**)&vl,  g_vl);
    cudaGetSymbolAddress((void**)&lnh, g_ln_hi);
    cudaGetSymbolAddress((void**)&lnl, g_ln_lo);
    cudaGetSymbolAddress((void**)&ath, g_at_hi);
    cudaGetSymbolAddress((void**)&atl, g_at_lo);
    cudaGetSymbolAddress((void**)&acth, g_act_hi);
    cudaGetSymbolAddress((void**)&actl, g_act_lo);
    cudaGetSymbolAddress((void**)&wqh, g_wqkv_hi);
    cudaGetSymbolAddress((void**)&wql, g_wqkv_lo);
    cudaGetSymbolAddress((void**)&waoh, g_wao_hi);
    cudaGetSymbolAddress((void**)&waol, g_wao_lo);
    cudaGetSymbolAddress((void**)&wfh, g_wfc_hi);
    cudaGetSymbolAddress((void**)&wfl, g_wfc_lo);
    cudaGetSymbolAddress((void**)&wph, g_wpo_hi);
    cudaGetSymbolAddress((void**)&wpl, g_wpo_lo);

    cudaFuncSetAttribute(attn_mma,     cudaFuncAttributeMaxDynamicSharedMemorySize, ATTN_SMEM);
    cudaFuncSetAttribute(hmma_gemm<0>, cudaFuncAttributeMaxDynamicSharedMemorySize, GEMM_SMEM);
    cudaFuncSetAttribute(hmma_gemm<1>, cudaFuncAttributeMaxDynamicSharedMemorySize, GEMM_SMEM);
    cudaFuncSetAttribute(hmma_gemm<3>, cudaFuncAttributeMaxDynamicSharedMemorySize, GEMM_SMEM);
    cudaFuncSetAttribute(hmma_gemm_fc, cudaFuncAttributeMaxDynamicSharedMemorySize, GEMM2_SMEM);

    // fused weight conversion + LN1 (single launch)
    cvt_ln1_kernel<<<CVT_BLOCKS + MM, 256>>>(w_qkv, w_ao, w_fc, w_po, x, ln1_g, ln1_b);

    // 2. QKV GEMM (M=4096, N=3072, K=1024), emit Q/K/V hi-lo [B,H,S,HD]
    hmma_gemm<0><<<dim3(3*EE/BN, MM/BM), GT, GEMM_SMEM>>>(
        lnh, lnl, wqh, wql, b_qkv, nullptr, nullptr, 3*EE, EE);
    // 3. HMMA causal flash attention (AQ=64, 2 CTAs/SM, LPT) -> at hi/lo
    attn_mma<<<dim3(SS/AQ, BB*HH), AT, ATTN_SMEM>>>(qh, ql, kh, kl, vh, vl, ath, atl);
    // 4. AO GEMM + residual -> x1 (fp32)
    hmma_gemm<1><<<dim3(EE/BN, MM/BM), GT, GEMM_SMEM>>>(
        ath, atl, waoh, waol, b_ao, x, x1, EE, EE);
    // 5. LN2 -> hi/lo
    ln_kernel<<<MM, 256>>>(x1, ln2_g, ln2_b, lnh, lnl);
    // 6. FC GEMM + gelu -> act hi/lo (128x128 tiles)
    hmma_gemm_fc<<<dim3(DFF/BN2, MM/BM2), GT, GEMM2_SMEM>>>(
        lnh, lnl, wfh, wfl, b_fc, DFF, EE);
    // 7. PO GEMM + residual -> out
    hmma_gemm<3><<<dim3(EE/BN, MM/BM), GT, GEMM_SMEM>>>(
        acth, actl, wph, wpl, b_po, x1, out, EE, DFF);
}